// round 11
// baseline (speedup 1.0000x reference)
#include <cuda_runtime.h>
#include <cuda_fp16.h>
#include <cstdint>
#include <math.h>

#define MAX_N 100000
#define MAX_E 1600000

// -------- scratch (static device globals; allocation-free) --------
static __device__ float g_bufA[(size_t)MAX_N * 128];
static __device__ float g_bufB[(size_t)MAX_N * 128];
static __device__ float g_dinv[MAX_N];
static __device__ int   g_indeg[MAX_N];
static __device__ int   g_cursor[MAX_N];
static __device__ int   g_offsets[MAX_N + 1];
static __device__ int   g_partials[1024];
static __device__ int   g_csr[MAX_E];
static __device__ float g_pool[128 * 64];
static __device__ int   g_cnt[128];
static __device__ __half g_W3h[256 * 136];   // Wt3 hi rows [0,128) + lo rows [128,256), stride 136
static __device__ __half g_W4h[128 * 136];   // Wt4 hi rows [0,64) + lo rows [64,128), stride 136

// -------- fp16 helpers --------
__device__ __forceinline__ void acc8(float* a, uint4 v) {
    __half2 h0 = *reinterpret_cast<__half2*>(&v.x);
    __half2 h1 = *reinterpret_cast<__half2*>(&v.y);
    __half2 h2 = *reinterpret_cast<__half2*>(&v.z);
    __half2 h3 = *reinterpret_cast<__half2*>(&v.w);
    float2 f0 = __half22float2(h0); a[0] += f0.x; a[1] += f0.y;
    float2 f1 = __half22float2(h1); a[2] += f1.x; a[3] += f1.y;
    float2 f2 = __half22float2(h2); a[4] += f2.x; a[5] += f2.y;
    float2 f3 = __half22float2(h3); a[6] += f3.x; a[7] += f3.y;
}

// pairwise fp16 add of two packed rows (4x HADD2)
__device__ __forceinline__ uint4 hadd2_4(uint4 a, uint4 b) {
    uint4 r;
    __half2 r0 = __hadd2(*reinterpret_cast<__half2*>(&a.x), *reinterpret_cast<__half2*>(&b.x));
    __half2 r1 = __hadd2(*reinterpret_cast<__half2*>(&a.y), *reinterpret_cast<__half2*>(&b.y));
    __half2 r2 = __hadd2(*reinterpret_cast<__half2*>(&a.z), *reinterpret_cast<__half2*>(&b.z));
    __half2 r3 = __hadd2(*reinterpret_cast<__half2*>(&a.w), *reinterpret_cast<__half2*>(&b.w));
    r.x = *reinterpret_cast<unsigned*>(&r0);
    r.y = *reinterpret_cast<unsigned*>(&r1);
    r.z = *reinterpret_cast<unsigned*>(&r2);
    r.w = *reinterpret_cast<unsigned*>(&r3);
    return r;
}

__device__ __forceinline__ uint4 pack8(const float* a) {
    __half2 h0 = __floats2half2_rn(a[0], a[1]);
    __half2 h1 = __floats2half2_rn(a[2], a[3]);
    __half2 h2 = __floats2half2_rn(a[4], a[5]);
    __half2 h3 = __floats2half2_rn(a[6], a[7]);
    uint4 r;
    r.x = *reinterpret_cast<unsigned*>(&h0);
    r.y = *reinterpret_cast<unsigned*>(&h1);
    r.z = *reinterpret_cast<unsigned*>(&h2);
    r.w = *reinterpret_cast<unsigned*>(&h3);
    return r;
}

// gather 8 features (uint4 of fp16) for node d, lane-chunk c8; o = self + sum(neighbors)
// 4-wide MLP loop with pairwise HADD2 pre-reduction (halves cvt/add instruction count)
template<int TPN>
__device__ __forceinline__ void gather8(const uint4* __restrict__ p4, int d, int c8, float* o) {
    float a0[8], a1[8];
    #pragma unroll
    for (int j = 0; j < 8; j++) { a0[j] = 0.f; a1[j] = 0.f; }
    acc8(a0, p4[(size_t)d * TPN + c8]);  // self loop
    const int s0 = g_offsets[d], s1 = g_offsets[d + 1];
    int e = s0;
    for (; e + 4 <= s1; e += 4) {
        int i0 = g_csr[e], i1 = g_csr[e + 1], i2 = g_csr[e + 2], i3 = g_csr[e + 3];
        uint4 v0 = __ldg(&p4[(size_t)i0 * TPN + c8]);
        uint4 v1 = __ldg(&p4[(size_t)i1 * TPN + c8]);
        uint4 v2 = __ldg(&p4[(size_t)i2 * TPN + c8]);
        uint4 v3 = __ldg(&p4[(size_t)i3 * TPN + c8]);
        acc8(a0, hadd2_4(v0, v1));
        acc8(a1, hadd2_4(v2, v3));
    }
    for (; e < s1; e++) {
        uint4 v = __ldg(&p4[(size_t)g_csr[e] * TPN + c8]);
        acc8(a0, v);
    }
    #pragma unroll
    for (int j = 0; j < 8; j++) o[j] = a0[j] + a1[j];
}

// -------- init + weight convert (fused; all independent work) --------
__global__ void k_init(const float* __restrict__ W3, const float* __restrict__ W4, int n) {
    int stride = gridDim.x * blockDim.x;
    int i = blockIdx.x * blockDim.x + threadIdx.x;
    for (int j = i; j < n; j += stride) { g_indeg[j] = 0; g_cursor[j] = 0; }
    for (int j = i; j < 128 * 64; j += stride) g_pool[j] = 0.f;
    if (i < 128) g_cnt[i] = 0;
    for (int j = i; j < 128 * 128; j += stride) {   // W3 [k][n] -> hi/lo [n][k]
        int k = j >> 7, nn = j & 127;
        float w = W3[j];
        __half hi = __float2half(w);
        g_W3h[nn * 136 + k] = hi;
        g_W3h[(128 + nn) * 136 + k] = __float2half(w - __half2float(hi));
    }
    for (int j = i; j < 128 * 64; j += stride) {    // W4 [k][n] -> hi/lo [n][k]
        int k = j >> 6, nn = j & 63;
        float w = W4[j];
        __half hi = __float2half(w);
        g_W4h[nn * 136 + k] = hi;
        g_W4h[(64 + nn) * 136 + k] = __float2half(w - __half2float(hi));
    }
}

__global__ void k_count(const int* __restrict__ ei, int E) {
    int stride = gridDim.x * blockDim.x;
    for (int e = blockIdx.x * blockDim.x + threadIdx.x; e < E; e += stride) {
        int d = ei[E + e];
        atomicAdd(&g_indeg[d], 1);
    }
}

__global__ void k_scan1(int n) {
    __shared__ int s[256];
    int t = threadIdx.x;
    int idx = blockIdx.x * 256 + t;
    int v = (idx < n) ? g_indeg[idx] : 0;
    if (idx < n) g_dinv[idx] = rsqrtf((float)(v + 1));  // +1 self loop
    s[t] = v;
    __syncthreads();
    #pragma unroll
    for (int off = 1; off < 256; off <<= 1) {
        int add = (t >= off) ? s[t - off] : 0;
        __syncthreads();
        s[t] += add;
        __syncthreads();
    }
    if (idx < n) g_offsets[idx] = s[t] - v;
    if (t == 255) g_partials[blockIdx.x] = s[255];
}

__global__ void k_scan2(int nb) {
    __shared__ int s[512];
    int t = threadIdx.x;
    int v = (t < nb) ? g_partials[t] : 0;
    s[t] = v;
    __syncthreads();
    #pragma unroll
    for (int off = 1; off < 512; off <<= 1) {
        int add = (t >= off) ? s[t - off] : 0;
        __syncthreads();
        s[t] += add;
        __syncthreads();
    }
    if (t < nb) g_partials[t] = s[t] - v;
}

__global__ void k_scan3(int n, int E) {
    int idx = blockIdx.x * 256 + threadIdx.x;
    if (idx < n) g_offsets[idx] += g_partials[blockIdx.x];
    if (idx == 0) g_offsets[n] = E;
}

__global__ void k_fill(const int* __restrict__ ei, int E) {
    int stride = gridDim.x * blockDim.x;
    for (int e = blockIdx.x * blockDim.x + threadIdx.x; e < E; e += stride) {
        int s = ei[e];
        int d = ei[E + e];
        int pos = g_offsets[d] + atomicAdd(&g_cursor[d], 1);
        g_csr[pos] = s;
    }
}

// -------- HMMA GEMM (no epilogue): out = in @ W, fp16 in/out, fp32 accum --------
// Double-fp16 weights (hi rows [0,Fo), lo rows [Fo,2Fo)); B-fragments via ldmatrix.x4
// (one x4 covers b0/b1 for TWO n-tiles: lanes 0-7 tile j @k0, 8-15 tile j @k0+8,
//  16-23 tile j+1 @k0, 24-31 tile j+1 @k0+8).
template<int Fi, int Fo>
__global__ void __launch_bounds__(256) k_hmma(const __half* __restrict__ in,
                                              const __half* __restrict__ Wt,
                                              __half* __restrict__ outh, int n) {
    constexpr int AS = Fi + 8;     // fp16 stride (136 = 17x16B): conflict-free ldmatrix
    extern __shared__ __half sm[];
    __half* sA = sm;               // [128][AS]
    __half* sW = sm + 128 * AS;    // [2*Fo][AS]  (hi then lo)
    const int t = threadIdx.x;
    const int base = blockIdx.x * 128;

    for (int i = t; i < 2 * Fo * AS / 8; i += 256)
        reinterpret_cast<uint4*>(sW)[i] = reinterpret_cast<const uint4*>(Wt)[i];
    constexpr int RU = Fi / 8;
    for (int i = t; i < 128 * RU; i += 256) {
        int r = i / RU, c = i % RU;
        uint4 v = (base + r < n)
            ? __ldg(reinterpret_cast<const uint4*>(in + (size_t)(base + r) * Fi) + c)
            : make_uint4(0u, 0u, 0u, 0u);
        reinterpret_cast<uint4*>(sA + r * AS)[c] = v;
    }
    __syncthreads();

    const int w = t >> 5, lane = t & 31;
    const int m0 = w * 16;
    constexpr int NT = Fo / 8;
    float acc[NT][4];
    #pragma unroll
    for (int j = 0; j < NT; j++) {
        acc[j][0] = 0.f; acc[j][1] = 0.f; acc[j][2] = 0.f; acc[j][3] = 0.f;
    }

    // A ldmatrix lane address (canonical m16k16 recipe)
    const int mm = lane >> 3;
    const int arow = m0 + (lane & 7) + 8 * (mm & 1);
    const int acol0 = 8 * (mm >> 1);
    // B ldmatrix.x4 lane address components
    const int brow = lane & 7;
    const int bnoff = (mm & 2) << 2;     // +8 rows for second tile of the pair
    const int bkoff = (mm & 1) << 3;     // +8 k for b1

    #pragma unroll
    for (int k0 = 0; k0 < Fi; k0 += 16) {
        uint32_t a0, a1, a2, a3;
        uint32_t saddr = (uint32_t)__cvta_generic_to_shared(sA + arow * AS + acol0 + k0);
        asm volatile("ldmatrix.sync.aligned.m8n8.x4.shared.b16 {%0,%1,%2,%3}, [%4];"
                     : "=r"(a0), "=r"(a1), "=r"(a2), "=r"(a3) : "r"(saddr));
        #pragma unroll
        for (int j = 0; j < NT; j += 2) {
            // hi weights: tiles j, j+1
            uint32_t b0, b1, b2, b3;
            uint32_t baddr = (uint32_t)__cvta_generic_to_shared(
                sW + (j * 8 + bnoff + brow) * AS + k0 + bkoff);
            asm volatile("ldmatrix.sync.aligned.m8n8.x4.shared.b16 {%0,%1,%2,%3}, [%4];"
                         : "=r"(b0), "=r"(b1), "=r"(b2), "=r"(b3) : "r"(baddr));
            asm volatile(
                "mma.sync.aligned.m16n8k16.row.col.f32.f16.f16.f32 "
                "{%0,%1,%2,%3}, {%4,%5,%6,%7}, {%8,%9}, {%0,%1,%2,%3};"
                : "+f"(acc[j][0]), "+f"(acc[j][1]), "+f"(acc[j][2]), "+f"(acc[j][3])
                : "r"(a0), "r"(a1), "r"(a2), "r"(a3), "r"(b0), "r"(b1));
            asm volatile(
                "mma.sync.aligned.m16n8k16.row.col.f32.f16.f16.f32 "
                "{%0,%1,%2,%3}, {%4,%5,%6,%7}, {%8,%9}, {%0,%1,%2,%3};"
                : "+f"(acc[j+1][0]), "+f"(acc[j+1][1]), "+f"(acc[j+1][2]), "+f"(acc[j+1][3])
                : "r"(a0), "r"(a1), "r"(a2), "r"(a3), "r"(b2), "r"(b3));
            // lo weights: tiles Fo+j, Fo+j+1
            uint32_t c0, c1, c2, c3;
            uint32_t caddr = (uint32_t)__cvta_generic_to_shared(
                sW + ((Fo + j * 8) + bnoff + brow) * AS + k0 + bkoff);
            asm volatile("ldmatrix.sync.aligned.m8n8.x4.shared.b16 {%0,%1,%2,%3}, [%4];"
                         : "=r"(c0), "=r"(c1), "=r"(c2), "=r"(c3) : "r"(caddr));
            asm volatile(
                "mma.sync.aligned.m16n8k16.row.col.f32.f16.f16.f32 "
                "{%0,%1,%2,%3}, {%4,%5,%6,%7}, {%8,%9}, {%0,%1,%2,%3};"
                : "+f"(acc[j][0]), "+f"(acc[j][1]), "+f"(acc[j][2]), "+f"(acc[j][3])
                : "r"(a0), "r"(a1), "r"(a2), "r"(a3), "r"(c0), "r"(c1));
            asm volatile(
                "mma.sync.aligned.m16n8k16.row.col.f32.f16.f16.f32 "
                "{%0,%1,%2,%3}, {%4,%5,%6,%7}, {%8,%9}, {%0,%1,%2,%3};"
                : "+f"(acc[j+1][0]), "+f"(acc[j+1][1]), "+f"(acc[j+1][2]), "+f"(acc[j+1][3])
                : "r"(a0), "r"(a1), "r"(a2), "r"(a3), "r"(c2), "r"(c3));
        }
    }

    const int r0 = base + m0 + (lane >> 2);
    const int col = (lane & 3) * 2;
    #pragma unroll
    for (int j = 0; j < NT; j++) {
        if (r0 < n) {
            __half2 h = __floats2half2_rn(acc[j][0], acc[j][1]);
            *reinterpret_cast<__half2*>(outh + (size_t)r0 * Fo + j * 8 + col) = h;
        }
        if (r0 + 8 < n) {
            __half2 h = __floats2half2_rn(acc[j][2], acc[j][3]);
            *reinterpret_cast<__half2*>(outh + (size_t)(r0 + 8) * Fo + j * 8 + col) = h;
        }
    }
}

// -------- scalar fused GEMM (L1 only): out = epi(in @ W); fp32 in, fp16 out --------
template<int Fi, int Fo, bool SCALE>
__global__ void __launch_bounds__(256) k_gemm(const float* __restrict__ in,
                                              const float* __restrict__ W,
                                              __half* __restrict__ outh, int n) {
    extern __shared__ float sWf[];
    for (int i = threadIdx.x; i < Fi * Fo; i += 256) sWf[i] = W[i];
    __syncthreads();

    constexpr int TPR = Fo / 4;
    constexpr int GRP = 256 / TPR;
    const int grp = threadIdx.x / TPR;
    const int c4  = threadIdx.x % TPR;
    constexpr int RPB = GRP * 4;

    for (int row0 = blockIdx.x * RPB + grp * 4; row0 < n; row0 += gridDim.x * RPB) {
        float4 acc[4];
        #pragma unroll
        for (int r = 0; r < 4; r++) acc[r] = make_float4(0.f, 0.f, 0.f, 0.f);
        const int rmax = n - row0;

        #pragma unroll 4
        for (int k = 0; k < Fi; k += 4) {
            float4 xr[4];
            #pragma unroll
            for (int r = 0; r < 4; r++)
                xr[r] = (r < rmax)
                    ? *reinterpret_cast<const float4*>(&in[(size_t)(row0 + r) * Fi + k])
                    : make_float4(0.f, 0.f, 0.f, 0.f);
            #pragma unroll
            for (int kk = 0; kk < 4; kk++) {
                float4 w = *reinterpret_cast<const float4*>(&sWf[(k + kk) * Fo + 4 * c4]);
                #pragma unroll
                for (int r = 0; r < 4; r++) {
                    float xv = (kk == 0) ? xr[r].x : (kk == 1) ? xr[r].y : (kk == 2) ? xr[r].z : xr[r].w;
                    acc[r].x += xv * w.x; acc[r].y += xv * w.y;
                    acc[r].z += xv * w.z; acc[r].w += xv * w.w;
                }
            }
        }
        #pragma unroll
        for (int r = 0; r < 4; r++) {
            if (r < rmax) {
                int row = row0 + r;
                float4 a = acc[r];
                if (SCALE) {
                    float dv = g_dinv[row];
                    a.x *= dv; a.y *= dv; a.z *= dv; a.w *= dv;
                }
                __half2 h0 = __floats2half2_rn(a.x, a.y);
                __half2 h1 = __floats2half2_rn(a.z, a.w);
                uint2 u; u.x = *reinterpret_cast<unsigned*>(&h0);
                u.y = *reinterpret_cast<unsigned*>(&h1);
                *reinterpret_cast<uint2*>(outh + (size_t)row * Fo + 4 * c4) = u;
            }
        }
    }
}

// -------- standalone aggregation (post-GEMM): out = dinv*tanh(dinv*agg+b), fp16 out --------
template<int F>
__global__ void __launch_bounds__(256) k_agg1(const __half* __restrict__ p,
                                              const float* __restrict__ bias,
                                              __half* __restrict__ outh, int n) {
    constexpr int TPN = F / 8;
    int t = blockIdx.x * 256 + threadIdx.x;
    int d = t / TPN;
    int c8 = t % TPN;
    if (d >= n) return;
    float s[8];
    gather8<TPN>(reinterpret_cast<const uint4*>(p), d, c8, s);
    float dv = g_dinv[d];
    const float* b = &bias[c8 * 8];
    float o[8];
    #pragma unroll
    for (int j = 0; j < 8; j++) o[j] = dv * tanhf(dv * s[j] + b[j]);
    *reinterpret_cast<uint4*>(outh + (size_t)d * F + c8 * 8) = pack8(o);
}

// -------- L2 fused: v16 = dinv*(agg p1) -> GEMM 16->128 -> tanh,dinv -> fp16 --------
__global__ void __launch_bounds__(256) k_l2fused(const __half* __restrict__ p1,
                                                 const float* __restrict__ W2,
                                                 const float* __restrict__ b2,
                                                 __half* __restrict__ outh, int n) {
    __shared__ float sV[128][16];
    __shared__ float sW[16 * 128];
    __shared__ float sB[128];
    int t = threadIdx.x;
    for (int i = t; i < 16 * 128; i += 256) sW[i] = W2[i];
    if (t < 128) sB[t] = b2[t];
    int base = blockIdx.x * 128;
    {
        int r = t >> 1, c8 = t & 1;
        int row = base + r;
        if (row < n) {
            float s[8];
            gather8<2>(reinterpret_cast<const uint4*>(p1), row, c8, s);
            float dv = g_dinv[row];
            #pragma unroll
            for (int j = 0; j < 8; j++) sV[r][c8 * 8 + j] = dv * s[j];
        }
    }
    __syncthreads();
    int grp = t >> 5, c4 = t & 31;
    #pragma unroll
    for (int it = 0; it < 4; it++) {
        int r0 = it * 32 + grp * 4;
        int row0 = base + r0;
        if (row0 >= n) continue;
        int rmax = n - row0;
        float4 acc[4];
        #pragma unroll
        for (int r = 0; r < 4; r++) acc[r] = make_float4(0.f, 0.f, 0.f, 0.f);
        #pragma unroll
        for (int k = 0; k < 16; k++) {
            float4 w = *reinterpret_cast<const float4*>(&sW[k * 128 + 4 * c4]);
            #pragma unroll
            for (int r = 0; r < 4; r++) {
                float xv = (r < rmax) ? sV[r0 + r][k] : 0.f;
                acc[r].x += xv * w.x; acc[r].y += xv * w.y;
                acc[r].z += xv * w.z; acc[r].w += xv * w.w;
            }
        }
        #pragma unroll
        for (int r = 0; r < 4; r++) {
            if (r < rmax) {
                int row = row0 + r;
                float dv = g_dinv[row];
                float4 b4 = *reinterpret_cast<const float4*>(&sB[4 * c4]);
                float o0 = dv * tanhf(acc[r].x + b4.x);
                float o1 = dv * tanhf(acc[r].y + b4.y);
                float o2 = dv * tanhf(acc[r].z + b4.z);
                float o3 = dv * tanhf(acc[r].w + b4.w);
                __half2 h0 = __floats2half2_rn(o0, o1);
                __half2 h1 = __floats2half2_rn(o2, o3);
                uint2 u; u.x = *reinterpret_cast<unsigned*>(&h0);
                u.y = *reinterpret_cast<unsigned*>(&h1);
                *reinterpret_cast<uint2*>(outh + (size_t)row * 128 + 4 * c4) = u;
            }
        }
    }
}

// -------- L5 fused: v64 = dinv*(agg p4) -> GEMM 64->64 -> tanh -> pool atomics --------
__global__ void __launch_bounds__(256) k_l5fused(const __half* __restrict__ p4in,
                                                 const float* __restrict__ W5,
                                                 const float* __restrict__ b5,
                                                 const int* __restrict__ batch, int n) {
    __shared__ float sV[64][64];
    __shared__ float sW[64 * 64];
    __shared__ float sB[64];
    int t = threadIdx.x;
    for (int i = t; i < 64 * 64; i += 256) sW[i] = W5[i];
    if (t < 64) sB[t] = b5[t];
    int base = blockIdx.x * 64;
    #pragma unroll
    for (int pass = 0; pass < 2; pass++) {
        int r = pass * 32 + (t >> 3);
        int c8 = t & 7;
        int row = base + r;
        if (row < n) {
            float s[8];
            gather8<8>(reinterpret_cast<const uint4*>(p4in), row, c8, s);
            float dv = g_dinv[row];
            #pragma unroll
            for (int j = 0; j < 8; j++) sV[r][c8 * 8 + j] = dv * s[j];
        }
    }
    __syncthreads();
    int grp = t >> 4, c4 = t & 15;
    int row0 = base + grp * 4;
    if (row0 >= n) return;
    int rmax = n - row0;
    float4 acc[4];
    #pragma unroll
    for (int r = 0; r < 4; r++) acc[r] = make_float4(0.f, 0.f, 0.f, 0.f);
    #pragma unroll 8
    for (int k = 0; k < 64; k++) {
        float4 w = *reinterpret_cast<const float4*>(&sW[k * 64 + 4 * c4]);
        #pragma unroll
        for (int r = 0; r < 4; r++) {
            float xv = (r < rmax) ? sV[grp * 4 + r][k] : 0.f;
            acc[r].x += xv * w.x; acc[r].y += xv * w.y;
            acc[r].z += xv * w.z; acc[r].w += xv * w.w;
        }
    }
    #pragma unroll
    for (int r = 0; r < 4; r++) {
        if (r < rmax) {
            int row = row0 + r;
            float4 b4 = *reinterpret_cast<const float4*>(&sB[4 * c4]);
            float o0 = tanhf(acc[r].x + b4.x);
            float o1 = tanhf(acc[r].y + b4.y);
            float o2 = tanhf(acc[r].z + b4.z);
            float o3 = tanhf(acc[r].w + b4.w);
            int g = batch[row];
            float* dst = &g_pool[g * 64 + 4 * c4];
            atomicAdd(dst + 0, o0); atomicAdd(dst + 1, o1);
            atomicAdd(dst + 2, o2); atomicAdd(dst + 3, o3);
            if (c4 == 0) atomicAdd(&g_cnt[g], 1);
        }
    }
}

__global__ void k_final(const float* __restrict__ Wc, const float* __restrict__ bc,
                        float* __restrict__ out) {
    int warp = (blockIdx.x * blockDim.x + threadIdx.x) / 32;
    int lane = threadIdx.x & 31;
    if (warp >= 128) return;
    float c = fmaxf((float)g_cnt[warp], 1.f);
    float s = g_pool[warp * 64 + lane] * Wc[lane] + g_pool[warp * 64 + lane + 32] * Wc[lane + 32];
    #pragma unroll
    for (int off = 16; off; off >>= 1) s += __shfl_down_sync(0xffffffffu, s, off);
    if (lane == 0) out[warp] = s / c + bc[0];
}

// -------- host side --------
static float* symA() { static float* p = nullptr; if (!p) cudaGetSymbolAddress((void**)&p, g_bufA); return p; }
static float* symB() { static float* p = nullptr; if (!p) cudaGetSymbolAddress((void**)&p, g_bufB); return p; }
static __half* symW3() { static __half* p = nullptr; if (!p) cudaGetSymbolAddress((void**)&p, g_W3h); return p; }
static __half* symW4() { static __half* p = nullptr; if (!p) cudaGetSymbolAddress((void**)&p, g_W4h); return p; }

extern "C" void kernel_launch(void* const* d_in, const int* in_sizes, int n_in,
                              void* d_out, int out_size) {
    const float* x     = (const float*)d_in[0];
    const int*   ei    = (const int*)d_in[1];     // int32 (JAX x64 disabled)
    const int*   batch = (const int*)d_in[2];     // int32
    const float* W1 = (const float*)d_in[3];  const float* b1 = (const float*)d_in[4];
    const float* W2 = (const float*)d_in[5];  const float* b2 = (const float*)d_in[6];
    const float* W3 = (const float*)d_in[7];  const float* b3 = (const float*)d_in[8];
    const float* W4 = (const float*)d_in[9];  const float* b4 = (const float*)d_in[10];
    const float* W5 = (const float*)d_in[11]; const float* b5 = (const float*)d_in[12];
    const float* Wc = (const float*)d_in[13]; const float* bc = (const float*)d_in[14];
    float* out = (float*)d_out;

    const int n = in_sizes[0] / 64;
    const int E = in_sizes[1] / 2;
    const int NB = (n + 255) / 256;

    __half* Ah = (__half*)symA();
    __half* Bh = (__half*)symB();

    constexpr int SM3 = (128 + 256) * 136 * 2;   // 104448 B (A + W3 hi/lo)
    constexpr int SM4 = (128 + 128) * 136 * 2;   // 69632 B  (A + W4 hi/lo)
    static bool attr_done = []() {
        cudaFuncSetAttribute((const void*)k_hmma<128, 128>,
                             cudaFuncAttributeMaxDynamicSharedMemorySize, SM3);
        cudaFuncSetAttribute((const void*)k_hmma<128, 64>,
                             cudaFuncAttributeMaxDynamicSharedMemorySize, SM4);
        return true;
    }();
    (void)attr_done;

    // ---- CSR build + weight conversion ----
    k_init<<<512, 256>>>(W3, W4, n);
    k_count<<<(E + 255) / 256, 256>>>(ei, E);
    k_scan1<<<NB, 256>>>(n);
    k_scan2<<<1, 512>>>(NB);
    k_scan3<<<NB, 256>>>(n, E);
    k_fill<<<(E + 255) / 256, 256>>>(ei, E);

    auto ablocks = [&](int F) { return (n * (F / 8) + 255) / 256; };

    // L1: 64->16 scalar transform-first: Ah = fp16(dinv * (x @ W1))
    k_gemm<64, 16, true><<<(n + 255) / 256, 256, 64 * 16 * 4>>>(x, W1, Ah, n);
    k_agg1<16><<<ablocks(16), 256>>>(Ah, b1, Bh, n);                 // Bh = p1

    // L2 fused: agg(p1) -> GEMM 16->128 -> tanh,dinv -> Ah = p2
    k_l2fused<<<(n + 127) / 128, 256>>>(Bh, W2, b2, Ah, n);

    // L3: 128->128 HMMA hi/lo (no epilogue), then agg
    k_hmma<128, 128><<<(n + 127) / 128, 256, SM3>>>(Ah, symW3(), Bh, n);
    k_agg1<128><<<ablocks(128), 256>>>(Bh, b3, Ah, n);               // Ah = p3

    // L4: 128->64 HMMA hi/lo, then agg
    k_hmma<128, 64><<<(n + 127) / 128, 256, SM4>>>(Ah, symW4(), Bh, n);
    k_agg1<64><<<ablocks(64), 256>>>(Bh, b4, Ah, n);                 // Ah = p4

    // L5 fused: agg(p4) -> GEMM 64->64 -> tanh -> pool atomics
    k_l5fused<<<(n + 63) / 64, 256>>>(Ah, W5, b5, batch, n);

    // ---- head ----
    k_final<<<32, 128>>>(Wc, bc, out);
    (void)out_size; (void)n_in;
}

// round 12
// speedup vs baseline: 1.1106x; 1.1106x over previous
#include <cuda_runtime.h>
#include <cuda_fp16.h>
#include <cstdint>
#include <math.h>

#define MAX_N 100000
#define MAX_E 1600000

// -------- scratch (static device globals; allocation-free) --------
static __device__ float g_bufA[(size_t)MAX_N * 128];
static __device__ float g_bufB[(size_t)MAX_N * 128];
static __device__ float g_dinv[MAX_N];
static __device__ int   g_indeg[MAX_N];
static __device__ int   g_cursor[MAX_N];
static __device__ int   g_offsets[MAX_N + 1];
static __device__ int   g_partials[1024];
static __device__ int   g_csr[MAX_E];
static __device__ float g_pool[128 * 64];
static __device__ int   g_cnt[128];
static __device__ __half g_W3h[256 * 136];   // Wt3 hi rows [0,128) + lo rows [128,256), stride 136
static __device__ __half g_W4h[128 * 136];   // Wt4 hi rows [0,64) + lo rows [64,128), stride 136
static __device__ __half g_W5h[128 * 72];    // Wt5 hi rows [0,64) + lo rows [64,128), stride 72

// -------- fp16 helpers --------
__device__ __forceinline__ void acc8(float* a, uint4 v) {
    __half2 h0 = *reinterpret_cast<__half2*>(&v.x);
    __half2 h1 = *reinterpret_cast<__half2*>(&v.y);
    __half2 h2 = *reinterpret_cast<__half2*>(&v.z);
    __half2 h3 = *reinterpret_cast<__half2*>(&v.w);
    float2 f0 = __half22float2(h0); a[0] += f0.x; a[1] += f0.y;
    float2 f1 = __half22float2(h1); a[2] += f1.x; a[3] += f1.y;
    float2 f2 = __half22float2(h2); a[4] += f2.x; a[5] += f2.y;
    float2 f3 = __half22float2(h3); a[6] += f3.x; a[7] += f3.y;
}

__device__ __forceinline__ uint4 hadd2_4(uint4 a, uint4 b) {
    uint4 r;
    __half2 r0 = __hadd2(*reinterpret_cast<__half2*>(&a.x), *reinterpret_cast<__half2*>(&b.x));
    __half2 r1 = __hadd2(*reinterpret_cast<__half2*>(&a.y), *reinterpret_cast<__half2*>(&b.y));
    __half2 r2 = __hadd2(*reinterpret_cast<__half2*>(&a.z), *reinterpret_cast<__half2*>(&b.z));
    __half2 r3 = __hadd2(*reinterpret_cast<__half2*>(&a.w), *reinterpret_cast<__half2*>(&b.w));
    r.x = *reinterpret_cast<unsigned*>(&r0);
    r.y = *reinterpret_cast<unsigned*>(&r1);
    r.z = *reinterpret_cast<unsigned*>(&r2);
    r.w = *reinterpret_cast<unsigned*>(&r3);
    return r;
}

__device__ __forceinline__ uint4 pack8(const float* a) {
    __half2 h0 = __floats2half2_rn(a[0], a[1]);
    __half2 h1 = __floats2half2_rn(a[2], a[3]);
    __half2 h2 = __floats2half2_rn(a[4], a[5]);
    __half2 h3 = __floats2half2_rn(a[6], a[7]);
    uint4 r;
    r.x = *reinterpret_cast<unsigned*>(&h0);
    r.y = *reinterpret_cast<unsigned*>(&h1);
    r.z = *reinterpret_cast<unsigned*>(&h2);
    r.w = *reinterpret_cast<unsigned*>(&h3);
    return r;
}

// gather 8 features (uint4 of fp16) for node d, chunk c8; o = self + sum(neighbors)
template<int TPN>
__device__ __forceinline__ void gather8(const uint4* __restrict__ p4, int d, int c8, float* o) {
    float a0[8], a1[8];
    #pragma unroll
    for (int j = 0; j < 8; j++) { a0[j] = 0.f; a1[j] = 0.f; }
    acc8(a0, p4[(size_t)d * TPN + c8]);  // self loop
    const int s0 = g_offsets[d], s1 = g_offsets[d + 1];
    int e = s0;
    for (; e + 4 <= s1; e += 4) {
        int i0 = g_csr[e], i1 = g_csr[e + 1], i2 = g_csr[e + 2], i3 = g_csr[e + 3];
        uint4 v0 = __ldg(&p4[(size_t)i0 * TPN + c8]);
        uint4 v1 = __ldg(&p4[(size_t)i1 * TPN + c8]);
        uint4 v2 = __ldg(&p4[(size_t)i2 * TPN + c8]);
        uint4 v3 = __ldg(&p4[(size_t)i3 * TPN + c8]);
        acc8(a0, hadd2_4(v0, v1));
        acc8(a1, hadd2_4(v2, v3));
    }
    for (; e < s1; e++) {
        uint4 v = __ldg(&p4[(size_t)g_csr[e] * TPN + c8]);
        acc8(a0, v);
    }
    #pragma unroll
    for (int j = 0; j < 8; j++) o[j] = a0[j] + a1[j];
}

// -------- init + weight hi/lo conversion --------
__global__ void k_init(const float* __restrict__ W3, const float* __restrict__ W4,
                       const float* __restrict__ W5, int n) {
    int stride = gridDim.x * blockDim.x;
    int i = blockIdx.x * blockDim.x + threadIdx.x;
    for (int j = i; j < n; j += stride) { g_indeg[j] = 0; g_cursor[j] = 0; }
    for (int j = i; j < 128 * 64; j += stride) g_pool[j] = 0.f;
    if (i < 128) g_cnt[i] = 0;
    for (int j = i; j < 128 * 128; j += stride) {
        int k = j >> 7, nn = j & 127;
        float w = W3[j];
        __half hi = __float2half(w);
        g_W3h[nn * 136 + k] = hi;
        g_W3h[(128 + nn) * 136 + k] = __float2half(w - __half2float(hi));
    }
    for (int j = i; j < 128 * 64; j += stride) {
        int k = j >> 6, nn = j & 63;
        float w = W4[j];
        __half hi = __float2half(w);
        g_W4h[nn * 136 + k] = hi;
        g_W4h[(64 + nn) * 136 + k] = __float2half(w - __half2float(hi));
    }
    for (int j = i; j < 64 * 64; j += stride) {
        int k = j >> 6, nn = j & 63;
        float w = W5[j];
        __half hi = __float2half(w);
        g_W5h[nn * 72 + k] = hi;
        g_W5h[(64 + nn) * 72 + k] = __float2half(w - __half2float(hi));
    }
}

__global__ void k_count(const int* __restrict__ ei, int E) {
    int stride = gridDim.x * blockDim.x;
    for (int e = blockIdx.x * blockDim.x + threadIdx.x; e < E; e += stride) {
        int d = ei[E + e];
        atomicAdd(&g_indeg[d], 1);
    }
}

__global__ void k_scan1(int n) {
    __shared__ int s[256];
    int t = threadIdx.x;
    int idx = blockIdx.x * 256 + t;
    int v = (idx < n) ? g_indeg[idx] : 0;
    if (idx < n) g_dinv[idx] = rsqrtf((float)(v + 1));
    s[t] = v;
    __syncthreads();
    #pragma unroll
    for (int off = 1; off < 256; off <<= 1) {
        int add = (t >= off) ? s[t - off] : 0;
        __syncthreads();
        s[t] += add;
        __syncthreads();
    }
    if (idx < n) g_offsets[idx] = s[t] - v;
    if (t == 255) g_partials[blockIdx.x] = s[255];
}

__global__ void k_scan2(int nb) {
    __shared__ int s[512];
    int t = threadIdx.x;
    int v = (t < nb) ? g_partials[t] : 0;
    s[t] = v;
    __syncthreads();
    #pragma unroll
    for (int off = 1; off < 512; off <<= 1) {
        int add = (t >= off) ? s[t - off] : 0;
        __syncthreads();
        s[t] += add;
        __syncthreads();
    }
    if (t < nb) g_partials[t] = s[t] - v;
}

__global__ void k_scan3(int n, int E) {
    int idx = blockIdx.x * 256 + threadIdx.x;
    if (idx < n) g_offsets[idx] += g_partials[blockIdx.x];
    if (idx == 0) g_offsets[n] = E;
}

__global__ void k_fill(const int* __restrict__ ei, int E) {
    int stride = gridDim.x * blockDim.x;
    for (int e = blockIdx.x * blockDim.x + threadIdx.x; e < E; e += stride) {
        int s = ei[e];
        int d = ei[E + e];
        int pos = g_offsets[d] + atomicAdd(&g_cursor[d], 1);
        g_csr[pos] = s;
    }
}

// -------- HMMA GEMM (standalone, no epilogue): out = in @ W --------
template<int Fi, int Fo>
__global__ void __launch_bounds__(256) k_hmma(const __half* __restrict__ in,
                                              const __half* __restrict__ Wt,
                                              __half* __restrict__ outh, int n) {
    constexpr int AS = Fi + 8;
    extern __shared__ __half sm[];
    __half* sA = sm;               // [128][AS]
    __half* sW = sm + 128 * AS;    // [2*Fo][AS]
    const int t = threadIdx.x;
    const int base = blockIdx.x * 128;

    for (int i = t; i < 2 * Fo * AS / 8; i += 256)
        reinterpret_cast<uint4*>(sW)[i] = reinterpret_cast<const uint4*>(Wt)[i];
    constexpr int RU = Fi / 8;
    for (int i = t; i < 128 * RU; i += 256) {
        int r = i / RU, c = i % RU;
        uint4 v = (base + r < n)
            ? __ldg(reinterpret_cast<const uint4*>(in + (size_t)(base + r) * Fi) + c)
            : make_uint4(0u, 0u, 0u, 0u);
        reinterpret_cast<uint4*>(sA + r * AS)[c] = v;
    }
    __syncthreads();

    const int w = t >> 5, lane = t & 31;
    const int m0 = w * 16;
    constexpr int NT = Fo / 8;
    float acc[NT][4];
    #pragma unroll
    for (int j = 0; j < NT; j++) {
        acc[j][0] = 0.f; acc[j][1] = 0.f; acc[j][2] = 0.f; acc[j][3] = 0.f;
    }
    const int mm = lane >> 3;
    const int arow = m0 + (lane & 7) + 8 * (mm & 1);
    const int acol0 = 8 * (mm >> 1);
    const int brow = lane & 7;
    const int bnoff = (mm & 2) << 2;
    const int bkoff = (mm & 1) << 3;

    #pragma unroll
    for (int k0 = 0; k0 < Fi; k0 += 16) {
        uint32_t a0, a1, a2, a3;
        uint32_t saddr = (uint32_t)__cvta_generic_to_shared(sA + arow * AS + acol0 + k0);
        asm volatile("ldmatrix.sync.aligned.m8n8.x4.shared.b16 {%0,%1,%2,%3}, [%4];"
                     : "=r"(a0), "=r"(a1), "=r"(a2), "=r"(a3) : "r"(saddr));
        #pragma unroll
        for (int j = 0; j < NT; j += 2) {
            uint32_t b0, b1, b2, b3;
            uint32_t baddr = (uint32_t)__cvta_generic_to_shared(
                sW + (j * 8 + bnoff + brow) * AS + k0 + bkoff);
            asm volatile("ldmatrix.sync.aligned.m8n8.x4.shared.b16 {%0,%1,%2,%3}, [%4];"
                         : "=r"(b0), "=r"(b1), "=r"(b2), "=r"(b3) : "r"(baddr));
            asm volatile(
                "mma.sync.aligned.m16n8k16.row.col.f32.f16.f16.f32 "
                "{%0,%1,%2,%3}, {%4,%5,%6,%7}, {%8,%9}, {%0,%1,%2,%3};"
                : "+f"(acc[j][0]), "+f"(acc[j][1]), "+f"(acc[j][2]), "+f"(acc[j][3])
                : "r"(a0), "r"(a1), "r"(a2), "r"(a3), "r"(b0), "r"(b1));
            asm volatile(
                "mma.sync.aligned.m16n8k16.row.col.f32.f16.f16.f32 "
                "{%0,%1,%2,%3}, {%4,%5,%6,%7}, {%8,%9}, {%0,%1,%2,%3};"
                : "+f"(acc[j+1][0]), "+f"(acc[j+1][1]), "+f"(acc[j+1][2]), "+f"(acc[j+1][3])
                : "r"(a0), "r"(a1), "r"(a2), "r"(a3), "r"(b2), "r"(b3));
            uint32_t c0, c1, c2, c3;
            uint32_t caddr = (uint32_t)__cvta_generic_to_shared(
                sW + ((Fo + j * 8) + bnoff + brow) * AS + k0 + bkoff);
            asm volatile("ldmatrix.sync.aligned.m8n8.x4.shared.b16 {%0,%1,%2,%3}, [%4];"
                         : "=r"(c0), "=r"(c1), "=r"(c2), "=r"(c3) : "r"(caddr));
            asm volatile(
                "mma.sync.aligned.m16n8k16.row.col.f32.f16.f16.f32 "
                "{%0,%1,%2,%3}, {%4,%5,%6,%7}, {%8,%9}, {%0,%1,%2,%3};"
                : "+f"(acc[j][0]), "+f"(acc[j][1]), "+f"(acc[j][2]), "+f"(acc[j][3])
                : "r"(a0), "r"(a1), "r"(a2), "r"(a3), "r"(c0), "r"(c1));
            asm volatile(
                "mma.sync.aligned.m16n8k16.row.col.f32.f16.f16.f32 "
                "{%0,%1,%2,%3}, {%4,%5,%6,%7}, {%8,%9}, {%0,%1,%2,%3};"
                : "+f"(acc[j+1][0]), "+f"(acc[j+1][1]), "+f"(acc[j+1][2]), "+f"(acc[j+1][3])
                : "r"(a0), "r"(a1), "r"(a2), "r"(a3), "r"(c2), "r"(c3));
        }
    }

    const int r0 = base + m0 + (lane >> 2);
    const int col = (lane & 3) * 2;
    #pragma unroll
    for (int j = 0; j < NT; j++) {
        if (r0 < n) {
            __half2 h = __floats2half2_rn(acc[j][0], acc[j][1]);
            *reinterpret_cast<__half2*>(outh + (size_t)r0 * Fo + j * 8 + col) = h;
        }
        if (r0 + 8 < n) {
            __half2 h = __floats2half2_rn(acc[j][2], acc[j][3]);
            *reinterpret_cast<__half2*>(outh + (size_t)(r0 + 8) * Fo + j * 8 + col) = h;
        }
    }
}

// -------- L3agg + L4 GEMM fused: p3 (gather+tanh) -> smem fp16 -> HMMA W4 -> h4 --------
__global__ void __launch_bounds__(256) k_l34(const __half* __restrict__ h3,
                                             const __half* __restrict__ Wt4,
                                             const float* __restrict__ b3,
                                             __half* __restrict__ outh, int n) {
    constexpr int AS = 136;        // Fi=128
    constexpr int Fo = 64;
    extern __shared__ __half sm[];
    __half* sA = sm;               // [128][136]  (p3 tile)
    __half* sW = sm + 128 * AS;    // [128][136]  (W4 hi/lo)
    const int t = threadIdx.x;
    const int base = blockIdx.x * 128;

    for (int i = t; i < 128 * AS / 8; i += 256)
        reinterpret_cast<uint4*>(sW)[i] = reinterpret_cast<const uint4*>(Wt4)[i];

    // phase A: p3 rows = dinv*tanh(dinv*agg(h3)+b3) into sA (fp16)
    #pragma unroll 1
    for (int it = 0; it < 8; it++) {
        int idx = it * 256 + t;
        int r = idx >> 4, c8 = idx & 15;
        int row = base + r;
        uint4 val = make_uint4(0u, 0u, 0u, 0u);
        if (row < n) {
            float s[8];
            gather8<16>(reinterpret_cast<const uint4*>(h3), row, c8, s);
            float dv = g_dinv[row];
            float o[8];
            #pragma unroll
            for (int j = 0; j < 8; j++) o[j] = dv * tanhf(dv * s[j] + __ldg(b3 + c8 * 8 + j));
            val = pack8(o);
        }
        *reinterpret_cast<uint4*>(sA + r * AS + c8 * 8) = val;
    }
    __syncthreads();

    // phase B: HMMA Fi=128 -> Fo=64 (hi/lo)
    const int w = t >> 5, lane = t & 31;
    const int m0 = w * 16;
    constexpr int NT = Fo / 8;   // 8
    float acc[NT][4];
    #pragma unroll
    for (int j = 0; j < NT; j++) {
        acc[j][0] = 0.f; acc[j][1] = 0.f; acc[j][2] = 0.f; acc[j][3] = 0.f;
    }
    const int mm = lane >> 3;
    const int arow = m0 + (lane & 7) + 8 * (mm & 1);
    const int acol0 = 8 * (mm >> 1);
    const int brow = lane & 7;
    const int bnoff = (mm & 2) << 2;
    const int bkoff = (mm & 1) << 3;

    #pragma unroll
    for (int k0 = 0; k0 < 128; k0 += 16) {
        uint32_t a0, a1, a2, a3;
        uint32_t saddr = (uint32_t)__cvta_generic_to_shared(sA + arow * AS + acol0 + k0);
        asm volatile("ldmatrix.sync.aligned.m8n8.x4.shared.b16 {%0,%1,%2,%3}, [%4];"
                     : "=r"(a0), "=r"(a1), "=r"(a2), "=r"(a3) : "r"(saddr));
        #pragma unroll
        for (int j = 0; j < NT; j += 2) {
            uint32_t b0, b1, b2, b3r;
            uint32_t baddr = (uint32_t)__cvta_generic_to_shared(
                sW + (j * 8 + bnoff + brow) * AS + k0 + bkoff);
            asm volatile("ldmatrix.sync.aligned.m8n8.x4.shared.b16 {%0,%1,%2,%3}, [%4];"
                         : "=r"(b0), "=r"(b1), "=r"(b2), "=r"(b3r) : "r"(baddr));
            asm volatile(
                "mma.sync.aligned.m16n8k16.row.col.f32.f16.f16.f32 "
                "{%0,%1,%2,%3}, {%4,%5,%6,%7}, {%8,%9}, {%0,%1,%2,%3};"
                : "+f"(acc[j][0]), "+f"(acc[j][1]), "+f"(acc[j][2]), "+f"(acc[j][3])
                : "r"(a0), "r"(a1), "r"(a2), "r"(a3), "r"(b0), "r"(b1));
            asm volatile(
                "mma.sync.aligned.m16n8k16.row.col.f32.f16.f16.f32 "
                "{%0,%1,%2,%3}, {%4,%5,%6,%7}, {%8,%9}, {%0,%1,%2,%3};"
                : "+f"(acc[j+1][0]), "+f"(acc[j+1][1]), "+f"(acc[j+1][2]), "+f"(acc[j+1][3])
                : "r"(a0), "r"(a1), "r"(a2), "r"(a3), "r"(b2), "r"(b3r));
            uint32_t c0, c1, c2, c3;
            uint32_t caddr = (uint32_t)__cvta_generic_to_shared(
                sW + ((Fo + j * 8) + bnoff + brow) * AS + k0 + bkoff);
            asm volatile("ldmatrix.sync.aligned.m8n8.x4.shared.b16 {%0,%1,%2,%3}, [%4];"
                         : "=r"(c0), "=r"(c1), "=r"(c2), "=r"(c3) : "r"(caddr));
            asm volatile(
                "mma.sync.aligned.m16n8k16.row.col.f32.f16.f16.f32 "
                "{%0,%1,%2,%3}, {%4,%5,%6,%7}, {%8,%9}, {%0,%1,%2,%3};"
                : "+f"(acc[j][0]), "+f"(acc[j][1]), "+f"(acc[j][2]), "+f"(acc[j][3])
                : "r"(a0), "r"(a1), "r"(a2), "r"(a3), "r"(c0), "r"(c1));
            asm volatile(
                "mma.sync.aligned.m16n8k16.row.col.f32.f16.f16.f32 "
                "{%0,%1,%2,%3}, {%4,%5,%6,%7}, {%8,%9}, {%0,%1,%2,%3};"
                : "+f"(acc[j+1][0]), "+f"(acc[j+1][1]), "+f"(acc[j+1][2]), "+f"(acc[j+1][3])
                : "r"(a0), "r"(a1), "r"(a2), "r"(a3), "r"(c2), "r"(c3));
        }
    }

    const int r0 = base + m0 + (lane >> 2);
    const int col = (lane & 3) * 2;
    #pragma unroll
    for (int j = 0; j < NT; j++) {
        if (r0 < n) {
            __half2 h = __floats2half2_rn(acc[j][0], acc[j][1]);
            *reinterpret_cast<__half2*>(outh + (size_t)r0 * Fo + j * 8 + col) = h;
        }
        if (r0 + 8 < n) {
            __half2 h = __floats2half2_rn(acc[j][2], acc[j][3]);
            *reinterpret_cast<__half2*>(outh + (size_t)(r0 + 8) * Fo + j * 8 + col) = h;
        }
    }
}

// -------- scalar fused GEMM (L1 only) --------
template<int Fi, int Fo, bool SCALE>
__global__ void __launch_bounds__(256) k_gemm(const float* __restrict__ in,
                                              const float* __restrict__ W,
                                              __half* __restrict__ outh, int n) {
    extern __shared__ float sWf[];
    for (int i = threadIdx.x; i < Fi * Fo; i += 256) sWf[i] = W[i];
    __syncthreads();

    constexpr int TPR = Fo / 4;
    constexpr int GRP = 256 / TPR;
    const int grp = threadIdx.x / TPR;
    const int c4  = threadIdx.x % TPR;
    constexpr int RPB = GRP * 4;

    for (int row0 = blockIdx.x * RPB + grp * 4; row0 < n; row0 += gridDim.x * RPB) {
        float4 acc[4];
        #pragma unroll
        for (int r = 0; r < 4; r++) acc[r] = make_float4(0.f, 0.f, 0.f, 0.f);
        const int rmax = n - row0;

        #pragma unroll 4
        for (int k = 0; k < Fi; k += 4) {
            float4 xr[4];
            #pragma unroll
            for (int r = 0; r < 4; r++)
                xr[r] = (r < rmax)
                    ? *reinterpret_cast<const float4*>(&in[(size_t)(row0 + r) * Fi + k])
                    : make_float4(0.f, 0.f, 0.f, 0.f);
            #pragma unroll
            for (int kk = 0; kk < 4; kk++) {
                float4 w = *reinterpret_cast<const float4*>(&sWf[(k + kk) * Fo + 4 * c4]);
                #pragma unroll
                for (int r = 0; r < 4; r++) {
                    float xv = (kk == 0) ? xr[r].x : (kk == 1) ? xr[r].y : (kk == 2) ? xr[r].z : xr[r].w;
                    acc[r].x += xv * w.x; acc[r].y += xv * w.y;
                    acc[r].z += xv * w.z; acc[r].w += xv * w.w;
                }
            }
        }
        #pragma unroll
        for (int r = 0; r < 4; r++) {
            if (r < rmax) {
                int row = row0 + r;
                float4 a = acc[r];
                if (SCALE) {
                    float dv = g_dinv[row];
                    a.x *= dv; a.y *= dv; a.z *= dv; a.w *= dv;
                }
                __half2 h0 = __floats2half2_rn(a.x, a.y);
                __half2 h1 = __floats2half2_rn(a.z, a.w);
                uint2 u; u.x = *reinterpret_cast<unsigned*>(&h0);
                u.y = *reinterpret_cast<unsigned*>(&h1);
                *reinterpret_cast<uint2*>(outh + (size_t)row * Fo + 4 * c4) = u;
            }
        }
    }
}

// -------- standalone aggregation: out = dinv*tanh(dinv*agg+b), fp16 out --------
template<int F>
__global__ void __launch_bounds__(256) k_agg1(const __half* __restrict__ p,
                                              const float* __restrict__ bias,
                                              __half* __restrict__ outh, int n) {
    constexpr int TPN = F / 8;
    int t = blockIdx.x * 256 + threadIdx.x;
    int d = t / TPN;
    int c8 = t % TPN;
    if (d >= n) return;
    float s[8];
    gather8<TPN>(reinterpret_cast<const uint4*>(p), d, c8, s);
    float dv = g_dinv[d];
    const float* b = &bias[c8 * 8];
    float o[8];
    #pragma unroll
    for (int j = 0; j < 8; j++) o[j] = dv * tanhf(dv * s[j] + b[j]);
    *reinterpret_cast<uint4*>(outh + (size_t)d * F + c8 * 8) = pack8(o);
}

// -------- L2 fused (scalar): v16 = dinv*(agg p1) -> GEMM 16->128 -> tanh,dinv --------
__global__ void __launch_bounds__(256) k_l2fused(const __half* __restrict__ p1,
                                                 const float* __restrict__ W2,
                                                 const float* __restrict__ b2,
                                                 __half* __restrict__ outh, int n) {
    __shared__ float sV[128][16];
    __shared__ float sW[16 * 128];
    __shared__ float sB[128];
    int t = threadIdx.x;
    for (int i = t; i < 16 * 128; i += 256) sW[i] = W2[i];
    if (t < 128) sB[t] = b2[t];
    int base = blockIdx.x * 128;
    {
        int r = t >> 1, c8 = t & 1;
        int row = base + r;
        if (row < n) {
            float s[8];
            gather8<2>(reinterpret_cast<const uint4*>(p1), row, c8, s);
            float dv = g_dinv[row];
            #pragma unroll
            for (int j = 0; j < 8; j++) sV[r][c8 * 8 + j] = dv * s[j];
        }
    }
    __syncthreads();
    int grp = t >> 5, c4 = t & 31;
    #pragma unroll
    for (int it = 0; it < 4; it++) {
        int r0 = it * 32 + grp * 4;
        int row0 = base + r0;
        if (row0 >= n) continue;
        int rmax = n - row0;
        float4 acc[4];
        #pragma unroll
        for (int r = 0; r < 4; r++) acc[r] = make_float4(0.f, 0.f, 0.f, 0.f);
        #pragma unroll
        for (int k = 0; k < 16; k++) {
            float4 w = *reinterpret_cast<const float4*>(&sW[k * 128 + 4 * c4]);
            #pragma unroll
            for (int r = 0; r < 4; r++) {
                float xv = (r < rmax) ? sV[r0 + r][k] : 0.f;
                acc[r].x += xv * w.x; acc[r].y += xv * w.y;
                acc[r].z += xv * w.z; acc[r].w += xv * w.w;
            }
        }
        #pragma unroll
        for (int r = 0; r < 4; r++) {
            if (r < rmax) {
                int row = row0 + r;
                float dv = g_dinv[row];
                float4 b4 = *reinterpret_cast<const float4*>(&sB[4 * c4]);
                float o0 = dv * tanhf(acc[r].x + b4.x);
                float o1 = dv * tanhf(acc[r].y + b4.y);
                float o2 = dv * tanhf(acc[r].z + b4.z);
                float o3 = dv * tanhf(acc[r].w + b4.w);
                __half2 h0 = __floats2half2_rn(o0, o1);
                __half2 h1 = __floats2half2_rn(o2, o3);
                uint2 u; u.x = *reinterpret_cast<unsigned*>(&h0);
                u.y = *reinterpret_cast<unsigned*>(&h1);
                *reinterpret_cast<uint2*>(outh + (size_t)row * 128 + 4 * c4) = u;
            }
        }
    }
}

// -------- L5 fused: v64 -> smem fp16 -> HMMA W5 hi/lo -> tanh -> pool atomics --------
__global__ void __launch_bounds__(256) k_l5fused(const __half* __restrict__ p4in,
                                                 const __half* __restrict__ Wt5,
                                                 const float* __restrict__ b5,
                                                 const int* __restrict__ batch, int n) {
    constexpr int AS = 72;
    __shared__ __half sV[64 * AS];
    __shared__ __half sW[128 * AS];
    __shared__ float sB[64];
    int t = threadIdx.x;
    int base = blockIdx.x * 64;
    for (int i = t; i < 128 * AS / 8; i += 256)
        reinterpret_cast<uint4*>(sW)[i] = reinterpret_cast<const uint4*>(Wt5)[i];
    if (t < 64) sB[t] = b5[t];
    // phase A: v64 = dinv*(agg p4) -> fp16 smem
    #pragma unroll
    for (int pass = 0; pass < 2; pass++) {
        int r = pass * 32 + (t >> 3);
        int c8 = t & 7;
        int row = base + r;
        uint4 val = make_uint4(0u, 0u, 0u, 0u);
        if (row < n) {
            float s[8];
            gather8<8>(reinterpret_cast<const uint4*>(p4in), row, c8, s);
            float dv = g_dinv[row];
            float o[8];
            #pragma unroll
            for (int j = 0; j < 8; j++) o[j] = dv * s[j];
            val = pack8(o);
        }
        *reinterpret_cast<uint4*>(sV + r * AS + c8 * 8) = val;
    }
    __syncthreads();

    // phase B: 8 warps = 4 m-slices x 2 n-halves; each warp 16 rows x 32 cols
    const int w = t >> 5, lane = t & 31;
    const int mw = w & 3, nw = w >> 2;
    const int m0 = mw * 16;
    float acc[4][4];
    #pragma unroll
    for (int j = 0; j < 4; j++) {
        acc[j][0] = 0.f; acc[j][1] = 0.f; acc[j][2] = 0.f; acc[j][3] = 0.f;
    }
    const int mm = lane >> 3;
    const int arow = m0 + (lane & 7) + 8 * (mm & 1);
    const int acol0 = 8 * (mm >> 1);
    const int brow = lane & 7;
    const int bnoff = (mm & 2) << 2;
    const int bkoff = (mm & 1) << 3;

    #pragma unroll
    for (int k0 = 0; k0 < 64; k0 += 16) {
        uint32_t a0, a1, a2, a3;
        uint32_t saddr = (uint32_t)__cvta_generic_to_shared(sV + arow * AS + acol0 + k0);
        asm volatile("ldmatrix.sync.aligned.m8n8.x4.shared.b16 {%0,%1,%2,%3}, [%4];"
                     : "=r"(a0), "=r"(a1), "=r"(a2), "=r"(a3) : "r"(saddr));
        #pragma unroll
        for (int jl = 0; jl < 4; jl += 2) {
            int j = nw * 4 + jl;
            uint32_t b0, b1, b2, b3r;
            uint32_t baddr = (uint32_t)__cvta_generic_to_shared(
                sW + (j * 8 + bnoff + brow) * AS + k0 + bkoff);
            asm volatile("ldmatrix.sync.aligned.m8n8.x4.shared.b16 {%0,%1,%2,%3}, [%4];"
                         : "=r"(b0), "=r"(b1), "=r"(b2), "=r"(b3r) : "r"(baddr));
            asm volatile(
                "mma.sync.aligned.m16n8k16.row.col.f32.f16.f16.f32 "
                "{%0,%1,%2,%3}, {%4,%5,%6,%7}, {%8,%9}, {%0,%1,%2,%3};"
                : "+f"(acc[jl][0]), "+f"(acc[jl][1]), "+f"(acc[jl][2]), "+f"(acc[jl][3])
                : "r"(a0), "r"(a1), "r"(a2), "r"(a3), "r"(b0), "r"(b1));
            asm volatile(
                "mma.sync.aligned.m16n8k16.row.col.f32.f16.f16.f32 "
                "{%0,%1,%2,%3}, {%4,%5,%6,%7}, {%8,%9}, {%0,%1,%2,%3};"
                : "+f"(acc[jl+1][0]), "+f"(acc[jl+1][1]), "+f"(acc[jl+1][2]), "+f"(acc[jl+1][3])
                : "r"(a0), "r"(a1), "r"(a2), "r"(a3), "r"(b2), "r"(b3r));
            uint32_t c0, c1, c2, c3;
            uint32_t caddr = (uint32_t)__cvta_generic_to_shared(
                sW + ((64 + j * 8) + bnoff + brow) * AS + k0 + bkoff);
            asm volatile("ldmatrix.sync.aligned.m8n8.x4.shared.b16 {%0,%1,%2,%3}, [%4];"
                         : "=r"(c0), "=r"(c1), "=r"(c2), "=r"(c3) : "r"(caddr));
            asm volatile(
                "mma.sync.aligned.m16n8k16.row.col.f32.f16.f16.f32 "
                "{%0,%1,%2,%3}, {%4,%5,%6,%7}, {%8,%9}, {%0,%1,%2,%3};"
                : "+f"(acc[jl][0]), "+f"(acc[jl][1]), "+f"(acc[jl][2]), "+f"(acc[jl][3])
                : "r"(a0), "r"(a1), "r"(a2), "r"(a3), "r"(c0), "r"(c1));
            asm volatile(
                "mma.sync.aligned.m16n8k16.row.col.f32.f16.f16.f32 "
                "{%0,%1,%2,%3}, {%4,%5,%6,%7}, {%8,%9}, {%0,%1,%2,%3};"
                : "+f"(acc[jl+1][0]), "+f"(acc[jl+1][1]), "+f"(acc[jl+1][2]), "+f"(acc[jl+1][3])
                : "r"(a0), "r"(a1), "r"(a2), "r"(a3), "r"(c2), "r"(c3));
        }
    }

    // epilogue: tanh(acc + b5) -> pool atomics
    const int row0 = base + m0 + (lane >> 2);
    const int row1 = row0 + 8;
    const int col = (lane & 3) * 2;
    const int g0 = (row0 < n) ? batch[row0] : 0;
    const int g1 = (row1 < n) ? batch[row1] : 0;
    #pragma unroll
    for (int jl = 0; jl < 4; jl++) {
        int ng = (nw * 4 + jl) * 8 + col;
        if (row0 < n) {
            atomicAdd(&g_pool[g0 * 64 + ng],     tanhf(acc[jl][0] + sB[ng]));
            atomicAdd(&g_pool[g0 * 64 + ng + 1], tanhf(acc[jl][1] + sB[ng + 1]));
        }
        if (row1 < n) {
            atomicAdd(&g_pool[g1 * 64 + ng],     tanhf(acc[jl][2] + sB[ng]));
            atomicAdd(&g_pool[g1 * 64 + ng + 1], tanhf(acc[jl][3] + sB[ng + 1]));
        }
    }
    if (nw == 0 && (lane & 3) == 0) {
        if (row0 < n) atomicAdd(&g_cnt[g0], 1);
        if (row1 < n) atomicAdd(&g_cnt[g1], 1);
    }
}

__global__ void k_final(const float* __restrict__ Wc, const float* __restrict__ bc,
                        float* __restrict__ out) {
    int warp = (blockIdx.x * blockDim.x + threadIdx.x) / 32;
    int lane = threadIdx.x & 31;
    if (warp >= 128) return;
    float c = fmaxf((float)g_cnt[warp], 1.f);
    float s = g_pool[warp * 64 + lane] * Wc[lane] + g_pool[warp * 64 + lane + 32] * Wc[lane + 32];
    #pragma unroll
    for (int off = 16; off; off >>= 1) s += __shfl_down_sync(0xffffffffu, s, off);
    if (lane == 0) out[warp] = s / c + bc[0];
}

// -------- host side --------
static float* symA() { static float* p = nullptr; if (!p) cudaGetSymbolAddress((void**)&p, g_bufA); return p; }
static float* symB() { static float* p = nullptr; if (!p) cudaGetSymbolAddress((void**)&p, g_bufB); return p; }
static __half* symW3() { static __half* p = nullptr; if (!p) cudaGetSymbolAddress((void**)&p, g_W3h); return p; }
static __half* symW4() { static __half* p = nullptr; if (!p) cudaGetSymbolAddress((void**)&p, g_W4h); return p; }
static __half* symW5() { static __half* p = nullptr; if (!p) cudaGetSymbolAddress((void**)&p, g_W5h); return p; }

extern "C" void kernel_launch(void* const* d_in, const int* in_sizes, int n_in,
                              void* d_out, int out_size) {
    const float* x     = (const float*)d_in[0];
    const int*   ei    = (const int*)d_in[1];     // int32 (JAX x64 disabled)
    const int*   batch = (const int*)d_in[2];     // int32
    const float* W1 = (const float*)d_in[3];  const float* b1 = (const float*)d_in[4];
    const float* W2 = (const float*)d_in[5];  const float* b2 = (const float*)d_in[6];
    const float* W3 = (const float*)d_in[7];  const float* b3 = (const float*)d_in[8];
    const float* W4 = (const float*)d_in[9];  const float* b4 = (const float*)d_in[10];
    const float* W5 = (const float*)d_in[11]; const float* b5 = (const float*)d_in[12];
    const float* Wc = (const float*)d_in[13]; const float* bc = (const float*)d_in[14];
    float* out = (float*)d_out;

    const int n = in_sizes[0] / 64;
    const int E = in_sizes[1] / 2;
    const int NB = (n + 255) / 256;

    __half* Ah = (__half*)symA();
    __half* Bh = (__half*)symB();

    constexpr int SM3  = (128 + 256) * 136 * 2;  // 104448 B (A + W3 hi/lo)
    constexpr int SM34 = (128 + 128) * 136 * 2;  // 69632 B  (p3 tile + W4 hi/lo)
    static bool attr_done = []() {
        cudaFuncSetAttribute((const void*)k_hmma<128, 128>,
                             cudaFuncAttributeMaxDynamicSharedMemorySize, SM3);
        cudaFuncSetAttribute((const void*)k_l34,
                             cudaFuncAttributeMaxDynamicSharedMemorySize, SM34);
        return true;
    }();
    (void)attr_done;

    // ---- CSR build + weight conversion ----
    k_init<<<512, 256>>>(W3, W4, W5, n);
    k_count<<<(E + 255) / 256, 256>>>(ei, E);
    k_scan1<<<NB, 256>>>(n);
    k_scan2<<<1, 512>>>(NB);
    k_scan3<<<NB, 256>>>(n, E);
    k_fill<<<(E + 255) / 256, 256>>>(ei, E);

    auto ablocks = [&](int F) { return (n * (F / 8) + 255) / 256; };

    // L1: 64->16 scalar transform-first: Ah = fp16(dinv * (x @ W1))
    k_gemm<64, 16, true><<<(n + 255) / 256, 256, 64 * 16 * 4>>>(x, W1, Ah, n);
    k_agg1<16><<<ablocks(16), 256>>>(Ah, b1, Bh, n);                 // Bh = p1

    // L2 fused: agg(p1) -> GEMM 16->128 -> tanh,dinv -> Ah = p2
    k_l2fused<<<(n + 127) / 128, 256>>>(Bh, W2, b2, Ah, n);

    // L3: 128->128 HMMA hi/lo -> Bh = h3
    k_hmma<128, 128><<<(n + 127) / 128, 256, SM3>>>(Ah, symW3(), Bh, n);

    // L3agg + L4 GEMM fused: gather h3, tanh -> p3 (smem) -> HMMA W4 -> Ah = h4
    k_l34<<<(n + 127) / 128, 256, SM34>>>(Bh, symW4(), b3, Ah, n);

    // L4 agg: Ah (h4) -> Bh = p4
    k_agg1<64><<<ablocks(64), 256>>>(Ah, b4, Bh, n);

    // L5 fused: agg(p4) -> HMMA W5 -> tanh -> pool atomics
    k_l5fused<<<(n + 63) / 64, 256>>>(Bh, symW5(), b5, batch, n);

    // ---- head ----
    k_final<<<32, 128>>>(Wc, bc, out);
    (void)out_size; (void)n_in;
}

// round 13
// speedup vs baseline: 1.1356x; 1.0224x over previous
#include <cuda_runtime.h>
#include <cuda_fp16.h>
#include <cstdint>
#include <math.h>

#define MAX_N 100000
#define MAX_E 1600000

// -------- scratch (static device globals; allocation-free) --------
static __device__ float g_bufA[(size_t)MAX_N * 128];
static __device__ float g_bufB[(size_t)MAX_N * 128];
static __device__ float g_dinv[MAX_N];
static __device__ int   g_indeg[MAX_N];
static __device__ int   g_cursor[MAX_N];
static __device__ int   g_offsets[MAX_N + 1];
static __device__ int   g_partials[1024];
static __device__ int   g_csr[MAX_E];
static __device__ float g_pool[128 * 64];
static __device__ int   g_cnt[128];
static __device__ __half g_W2h[256 * 24];    // Wt2 hi rows [0,128) + lo rows [128,256), stride 24
static __device__ __half g_W3h[256 * 136];   // Wt3 hi rows [0,128) + lo rows [128,256), stride 136
static __device__ __half g_W4h[128 * 136];   // Wt4 hi rows [0,64) + lo rows [64,128), stride 136
static __device__ __half g_W5h[128 * 72];    // Wt5 hi rows [0,64) + lo rows [64,128), stride 72

// -------- fp16 helpers --------
__device__ __forceinline__ void acc8(float* a, uint4 v) {
    __half2 h0 = *reinterpret_cast<__half2*>(&v.x);
    __half2 h1 = *reinterpret_cast<__half2*>(&v.y);
    __half2 h2 = *reinterpret_cast<__half2*>(&v.z);
    __half2 h3 = *reinterpret_cast<__half2*>(&v.w);
    float2 f0 = __half22float2(h0); a[0] += f0.x; a[1] += f0.y;
    float2 f1 = __half22float2(h1); a[2] += f1.x; a[3] += f1.y;
    float2 f2 = __half22float2(h2); a[4] += f2.x; a[5] += f2.y;
    float2 f3 = __half22float2(h3); a[6] += f3.x; a[7] += f3.y;
}

__device__ __forceinline__ uint4 hadd2_4(uint4 a, uint4 b) {
    uint4 r;
    __half2 r0 = __hadd2(*reinterpret_cast<__half2*>(&a.x), *reinterpret_cast<__half2*>(&b.x));
    __half2 r1 = __hadd2(*reinterpret_cast<__half2*>(&a.y), *reinterpret_cast<__half2*>(&b.y));
    __half2 r2 = __hadd2(*reinterpret_cast<__half2*>(&a.z), *reinterpret_cast<__half2*>(&b.z));
    __half2 r3 = __hadd2(*reinterpret_cast<__half2*>(&a.w), *reinterpret_cast<__half2*>(&b.w));
    r.x = *reinterpret_cast<unsigned*>(&r0);
    r.y = *reinterpret_cast<unsigned*>(&r1);
    r.z = *reinterpret_cast<unsigned*>(&r2);
    r.w = *reinterpret_cast<unsigned*>(&r3);
    return r;
}

__device__ __forceinline__ uint4 pack8(const float* a) {
    __half2 h0 = __floats2half2_rn(a[0], a[1]);
    __half2 h1 = __floats2half2_rn(a[2], a[3]);
    __half2 h2 = __floats2half2_rn(a[4], a[5]);
    __half2 h3 = __floats2half2_rn(a[6], a[7]);
    uint4 r;
    r.x = *reinterpret_cast<unsigned*>(&h0);
    r.y = *reinterpret_cast<unsigned*>(&h1);
    r.z = *reinterpret_cast<unsigned*>(&h2);
    r.w = *reinterpret_cast<unsigned*>(&h3);
    return r;
}

// gather 8 features (uint4 of fp16) for node d, chunk c8; o = self + sum(neighbors)
template<int TPN>
__device__ __forceinline__ void gather8(const uint4* __restrict__ p4, int d, int c8, float* o) {
    float a0[8], a1[8];
    #pragma unroll
    for (int j = 0; j < 8; j++) { a0[j] = 0.f; a1[j] = 0.f; }
    acc8(a0, p4[(size_t)d * TPN + c8]);  // self loop
    const int s0 = g_offsets[d], s1 = g_offsets[d + 1];
    int e = s0;
    for (; e + 4 <= s1; e += 4) {
        int i0 = g_csr[e], i1 = g_csr[e + 1], i2 = g_csr[e + 2], i3 = g_csr[e + 3];
        uint4 v0 = __ldg(&p4[(size_t)i0 * TPN + c8]);
        uint4 v1 = __ldg(&p4[(size_t)i1 * TPN + c8]);
        uint4 v2 = __ldg(&p4[(size_t)i2 * TPN + c8]);
        uint4 v3 = __ldg(&p4[(size_t)i3 * TPN + c8]);
        acc8(a0, hadd2_4(v0, v1));
        acc8(a1, hadd2_4(v2, v3));
    }
    for (; e < s1; e++) {
        uint4 v = __ldg(&p4[(size_t)g_csr[e] * TPN + c8]);
        acc8(a0, v);
    }
    #pragma unroll
    for (int j = 0; j < 8; j++) o[j] = a0[j] + a1[j];
}

// -------- init + weight hi/lo conversion --------
__global__ void k_init(const float* __restrict__ W2, const float* __restrict__ W3,
                       const float* __restrict__ W4, const float* __restrict__ W5, int n) {
    int stride = gridDim.x * blockDim.x;
    int i = blockIdx.x * blockDim.x + threadIdx.x;
    for (int j = i; j < n; j += stride) { g_indeg[j] = 0; g_cursor[j] = 0; }
    for (int j = i; j < 128 * 64; j += stride) g_pool[j] = 0.f;
    if (i < 128) g_cnt[i] = 0;
    for (int j = i; j < 16 * 128; j += stride) {    // W2 [k=16][n=128] -> hi/lo [n][k] stride 24
        int k = j >> 7, nn = j & 127;
        float w = W2[j];
        __half hi = __float2half(w);
        g_W2h[nn * 24 + k] = hi;
        g_W2h[(128 + nn) * 24 + k] = __float2half(w - __half2float(hi));
    }
    for (int j = i; j < 128 * 128; j += stride) {
        int k = j >> 7, nn = j & 127;
        float w = W3[j];
        __half hi = __float2half(w);
        g_W3h[nn * 136 + k] = hi;
        g_W3h[(128 + nn) * 136 + k] = __float2half(w - __half2float(hi));
    }
    for (int j = i; j < 128 * 64; j += stride) {
        int k = j >> 6, nn = j & 63;
        float w = W4[j];
        __half hi = __float2half(w);
        g_W4h[nn * 136 + k] = hi;
        g_W4h[(64 + nn) * 136 + k] = __float2half(w - __half2float(hi));
    }
    for (int j = i; j < 64 * 64; j += stride) {
        int k = j >> 6, nn = j & 63;
        float w = W5[j];
        __half hi = __float2half(w);
        g_W5h[nn * 72 + k] = hi;
        g_W5h[(64 + nn) * 72 + k] = __float2half(w - __half2float(hi));
    }
}

__global__ void k_count(const int* __restrict__ ei, int E) {
    int stride = gridDim.x * blockDim.x;
    for (int e = blockIdx.x * blockDim.x + threadIdx.x; e < E; e += stride) {
        int d = ei[E + e];
        atomicAdd(&g_indeg[d], 1);
    }
}

__global__ void k_scan1(int n) {
    __shared__ int s[256];
    int t = threadIdx.x;
    int idx = blockIdx.x * 256 + t;
    int v = (idx < n) ? g_indeg[idx] : 0;
    if (idx < n) g_dinv[idx] = rsqrtf((float)(v + 1));
    s[t] = v;
    __syncthreads();
    #pragma unroll
    for (int off = 1; off < 256; off <<= 1) {
        int add = (t >= off) ? s[t - off] : 0;
        __syncthreads();
        s[t] += add;
        __syncthreads();
    }
    if (idx < n) g_offsets[idx] = s[t] - v;
    if (t == 255) g_partials[blockIdx.x] = s[255];
}

__global__ void k_scan2(int nb) {
    __shared__ int s[512];
    int t = threadIdx.x;
    int v = (t < nb) ? g_partials[t] : 0;
    s[t] = v;
    __syncthreads();
    #pragma unroll
    for (int off = 1; off < 512; off <<= 1) {
        int add = (t >= off) ? s[t - off] : 0;
        __syncthreads();
        s[t] += add;
        __syncthreads();
    }
    if (t < nb) g_partials[t] = s[t] - v;
}

__global__ void k_scan3(int n, int E) {
    int idx = blockIdx.x * 256 + threadIdx.x;
    if (idx < n) g_offsets[idx] += g_partials[blockIdx.x];
    if (idx == 0) g_offsets[n] = E;
}

__global__ void k_fill(const int* __restrict__ ei, int E) {
    int stride = gridDim.x * blockDim.x;
    for (int e = blockIdx.x * blockDim.x + threadIdx.x; e < E; e += stride) {
        int s = ei[e];
        int d = ei[E + e];
        int pos = g_offsets[d] + atomicAdd(&g_cursor[d], 1);
        g_csr[pos] = s;
    }
}

// -------- HMMA GEMM (standalone, no epilogue): out = in @ W --------
template<int Fi, int Fo>
__global__ void __launch_bounds__(256) k_hmma(const __half* __restrict__ in,
                                              const __half* __restrict__ Wt,
                                              __half* __restrict__ outh, int n) {
    constexpr int AS = Fi + 8;
    extern __shared__ __half sm[];
    __half* sA = sm;               // [128][AS]
    __half* sW = sm + 128 * AS;    // [2*Fo][AS]
    const int t = threadIdx.x;
    const int base = blockIdx.x * 128;

    for (int i = t; i < 2 * Fo * AS / 8; i += 256)
        reinterpret_cast<uint4*>(sW)[i] = reinterpret_cast<const uint4*>(Wt)[i];
    constexpr int RU = Fi / 8;
    for (int i = t; i < 128 * RU; i += 256) {
        int r = i / RU, c = i % RU;
        uint4 v = (base + r < n)
            ? __ldg(reinterpret_cast<const uint4*>(in + (size_t)(base + r) * Fi) + c)
            : make_uint4(0u, 0u, 0u, 0u);
        reinterpret_cast<uint4*>(sA + r * AS)[c] = v;
    }
    __syncthreads();

    const int w = t >> 5, lane = t & 31;
    const int m0 = w * 16;
    constexpr int NT = Fo / 8;
    float acc[NT][4];
    #pragma unroll
    for (int j = 0; j < NT; j++) {
        acc[j][0] = 0.f; acc[j][1] = 0.f; acc[j][2] = 0.f; acc[j][3] = 0.f;
    }
    const int mm = lane >> 3;
    const int arow = m0 + (lane & 7) + 8 * (mm & 1);
    const int acol0 = 8 * (mm >> 1);
    const int brow = lane & 7;
    const int bnoff = (mm & 2) << 2;
    const int bkoff = (mm & 1) << 3;

    #pragma unroll
    for (int k0 = 0; k0 < Fi; k0 += 16) {
        uint32_t a0, a1, a2, a3;
        uint32_t saddr = (uint32_t)__cvta_generic_to_shared(sA + arow * AS + acol0 + k0);
        asm volatile("ldmatrix.sync.aligned.m8n8.x4.shared.b16 {%0,%1,%2,%3}, [%4];"
                     : "=r"(a0), "=r"(a1), "=r"(a2), "=r"(a3) : "r"(saddr));
        #pragma unroll
        for (int j = 0; j < NT; j += 2) {
            uint32_t b0, b1, b2, b3;
            uint32_t baddr = (uint32_t)__cvta_generic_to_shared(
                sW + (j * 8 + bnoff + brow) * AS + k0 + bkoff);
            asm volatile("ldmatrix.sync.aligned.m8n8.x4.shared.b16 {%0,%1,%2,%3}, [%4];"
                         : "=r"(b0), "=r"(b1), "=r"(b2), "=r"(b3) : "r"(baddr));
            asm volatile(
                "mma.sync.aligned.m16n8k16.row.col.f32.f16.f16.f32 "
                "{%0,%1,%2,%3}, {%4,%5,%6,%7}, {%8,%9}, {%0,%1,%2,%3};"
                : "+f"(acc[j][0]), "+f"(acc[j][1]), "+f"(acc[j][2]), "+f"(acc[j][3])
                : "r"(a0), "r"(a1), "r"(a2), "r"(a3), "r"(b0), "r"(b1));
            asm volatile(
                "mma.sync.aligned.m16n8k16.row.col.f32.f16.f16.f32 "
                "{%0,%1,%2,%3}, {%4,%5,%6,%7}, {%8,%9}, {%0,%1,%2,%3};"
                : "+f"(acc[j+1][0]), "+f"(acc[j+1][1]), "+f"(acc[j+1][2]), "+f"(acc[j+1][3])
                : "r"(a0), "r"(a1), "r"(a2), "r"(a3), "r"(b2), "r"(b3));
            uint32_t c0, c1, c2, c3;
            uint32_t caddr = (uint32_t)__cvta_generic_to_shared(
                sW + ((Fo + j * 8) + bnoff + brow) * AS + k0 + bkoff);
            asm volatile("ldmatrix.sync.aligned.m8n8.x4.shared.b16 {%0,%1,%2,%3}, [%4];"
                         : "=r"(c0), "=r"(c1), "=r"(c2), "=r"(c3) : "r"(caddr));
            asm volatile(
                "mma.sync.aligned.m16n8k16.row.col.f32.f16.f16.f32 "
                "{%0,%1,%2,%3}, {%4,%5,%6,%7}, {%8,%9}, {%0,%1,%2,%3};"
                : "+f"(acc[j][0]), "+f"(acc[j][1]), "+f"(acc[j][2]), "+f"(acc[j][3])
                : "r"(a0), "r"(a1), "r"(a2), "r"(a3), "r"(c0), "r"(c1));
            asm volatile(
                "mma.sync.aligned.m16n8k16.row.col.f32.f16.f16.f32 "
                "{%0,%1,%2,%3}, {%4,%5,%6,%7}, {%8,%9}, {%0,%1,%2,%3};"
                : "+f"(acc[j+1][0]), "+f"(acc[j+1][1]), "+f"(acc[j+1][2]), "+f"(acc[j+1][3])
                : "r"(a0), "r"(a1), "r"(a2), "r"(a3), "r"(c2), "r"(c3));
        }
    }

    const int r0 = base + m0 + (lane >> 2);
    const int col = (lane & 3) * 2;
    #pragma unroll
    for (int j = 0; j < NT; j++) {
        if (r0 < n) {
            __half2 h = __floats2half2_rn(acc[j][0], acc[j][1]);
            *reinterpret_cast<__half2*>(outh + (size_t)r0 * Fo + j * 8 + col) = h;
        }
        if (r0 + 8 < n) {
            __half2 h = __floats2half2_rn(acc[j][2], acc[j][3]);
            *reinterpret_cast<__half2*>(outh + (size_t)(r0 + 8) * Fo + j * 8 + col) = h;
        }
    }
}

// -------- L3agg + L4 GEMM fused: p3 (gather+tanh) -> smem fp16 -> HMMA W4 -> h4 --------
__global__ void __launch_bounds__(256) k_l34(const __half* __restrict__ h3,
                                             const __half* __restrict__ Wt4,
                                             const float* __restrict__ b3,
                                             __half* __restrict__ outh, int n) {
    constexpr int AS = 136;        // Fi=128
    constexpr int Fo = 64;
    extern __shared__ __half sm[];
    __half* sA = sm;               // [128][136]  (p3 tile)
    __half* sW = sm + 128 * AS;    // [128][136]  (W4 hi/lo)
    const int t = threadIdx.x;
    const int base = blockIdx.x * 128;

    for (int i = t; i < 128 * AS / 8; i += 256)
        reinterpret_cast<uint4*>(sW)[i] = reinterpret_cast<const uint4*>(Wt4)[i];

    // phase A: p3 rows = dinv*tanh(dinv*agg(h3)+b3) into sA (fp16)
    #pragma unroll 1
    for (int it = 0; it < 8; it++) {
        int idx = it * 256 + t;
        int r = idx >> 4, c8 = idx & 15;
        int row = base + r;
        uint4 val = make_uint4(0u, 0u, 0u, 0u);
        if (row < n) {
            float s[8];
            gather8<16>(reinterpret_cast<const uint4*>(h3), row, c8, s);
            float dv = g_dinv[row];
            float o[8];
            #pragma unroll
            for (int j = 0; j < 8; j++) o[j] = dv * tanhf(dv * s[j] + __ldg(b3 + c8 * 8 + j));
            val = pack8(o);
        }
        *reinterpret_cast<uint4*>(sA + r * AS + c8 * 8) = val;
    }
    __syncthreads();

    // phase B: HMMA Fi=128 -> Fo=64 (hi/lo)
    const int w = t >> 5, lane = t & 31;
    const int m0 = w * 16;
    constexpr int NT = Fo / 8;   // 8
    float acc[NT][4];
    #pragma unroll
    for (int j = 0; j < NT; j++) {
        acc[j][0] = 0.f; acc[j][1] = 0.f; acc[j][2] = 0.f; acc[j][3] = 0.f;
    }
    const int mm = lane >> 3;
    const int arow = m0 + (lane & 7) + 8 * (mm & 1);
    const int acol0 = 8 * (mm >> 1);
    const int brow = lane & 7;
    const int bnoff = (mm & 2) << 2;
    const int bkoff = (mm & 1) << 3;

    #pragma unroll
    for (int k0 = 0; k0 < 128; k0 += 16) {
        uint32_t a0, a1, a2, a3;
        uint32_t saddr = (uint32_t)__cvta_generic_to_shared(sA + arow * AS + acol0 + k0);
        asm volatile("ldmatrix.sync.aligned.m8n8.x4.shared.b16 {%0,%1,%2,%3}, [%4];"
                     : "=r"(a0), "=r"(a1), "=r"(a2), "=r"(a3) : "r"(saddr));
        #pragma unroll
        for (int j = 0; j < NT; j += 2) {
            uint32_t b0, b1, b2, b3r;
            uint32_t baddr = (uint32_t)__cvta_generic_to_shared(
                sW + (j * 8 + bnoff + brow) * AS + k0 + bkoff);
            asm volatile("ldmatrix.sync.aligned.m8n8.x4.shared.b16 {%0,%1,%2,%3}, [%4];"
                         : "=r"(b0), "=r"(b1), "=r"(b2), "=r"(b3r) : "r"(baddr));
            asm volatile(
                "mma.sync.aligned.m16n8k16.row.col.f32.f16.f16.f32 "
                "{%0,%1,%2,%3}, {%4,%5,%6,%7}, {%8,%9}, {%0,%1,%2,%3};"
                : "+f"(acc[j][0]), "+f"(acc[j][1]), "+f"(acc[j][2]), "+f"(acc[j][3])
                : "r"(a0), "r"(a1), "r"(a2), "r"(a3), "r"(b0), "r"(b1));
            asm volatile(
                "mma.sync.aligned.m16n8k16.row.col.f32.f16.f16.f32 "
                "{%0,%1,%2,%3}, {%4,%5,%6,%7}, {%8,%9}, {%0,%1,%2,%3};"
                : "+f"(acc[j+1][0]), "+f"(acc[j+1][1]), "+f"(acc[j+1][2]), "+f"(acc[j+1][3])
                : "r"(a0), "r"(a1), "r"(a2), "r"(a3), "r"(b2), "r"(b3r));
            uint32_t c0, c1, c2, c3;
            uint32_t caddr = (uint32_t)__cvta_generic_to_shared(
                sW + ((Fo + j * 8) + bnoff + brow) * AS + k0 + bkoff);
            asm volatile("ldmatrix.sync.aligned.m8n8.x4.shared.b16 {%0,%1,%2,%3}, [%4];"
                         : "=r"(c0), "=r"(c1), "=r"(c2), "=r"(c3) : "r"(caddr));
            asm volatile(
                "mma.sync.aligned.m16n8k16.row.col.f32.f16.f16.f32 "
                "{%0,%1,%2,%3}, {%4,%5,%6,%7}, {%8,%9}, {%0,%1,%2,%3};"
                : "+f"(acc[j][0]), "+f"(acc[j][1]), "+f"(acc[j][2]), "+f"(acc[j][3])
                : "r"(a0), "r"(a1), "r"(a2), "r"(a3), "r"(c0), "r"(c1));
            asm volatile(
                "mma.sync.aligned.m16n8k16.row.col.f32.f16.f16.f32 "
                "{%0,%1,%2,%3}, {%4,%5,%6,%7}, {%8,%9}, {%0,%1,%2,%3};"
                : "+f"(acc[j+1][0]), "+f"(acc[j+1][1]), "+f"(acc[j+1][2]), "+f"(acc[j+1][3])
                : "r"(a0), "r"(a1), "r"(a2), "r"(a3), "r"(c2), "r"(c3));
        }
    }

    const int r0 = base + m0 + (lane >> 2);
    const int col = (lane & 3) * 2;
    #pragma unroll
    for (int j = 0; j < NT; j++) {
        if (r0 < n) {
            __half2 h = __floats2half2_rn(acc[j][0], acc[j][1]);
            *reinterpret_cast<__half2*>(outh + (size_t)r0 * Fo + j * 8 + col) = h;
        }
        if (r0 + 8 < n) {
            __half2 h = __floats2half2_rn(acc[j][2], acc[j][3]);
            *reinterpret_cast<__half2*>(outh + (size_t)(r0 + 8) * Fo + j * 8 + col) = h;
        }
    }
}

// -------- scalar fused GEMM (L1 only) --------
template<int Fi, int Fo, bool SCALE>
__global__ void __launch_bounds__(256) k_gemm(const float* __restrict__ in,
                                              const float* __restrict__ W,
                                              __half* __restrict__ outh, int n) {
    extern __shared__ float sWf[];
    for (int i = threadIdx.x; i < Fi * Fo; i += 256) sWf[i] = W[i];
    __syncthreads();

    constexpr int TPR = Fo / 4;
    constexpr int GRP = 256 / TPR;
    const int grp = threadIdx.x / TPR;
    const int c4  = threadIdx.x % TPR;
    constexpr int RPB = GRP * 4;

    for (int row0 = blockIdx.x * RPB + grp * 4; row0 < n; row0 += gridDim.x * RPB) {
        float4 acc[4];
        #pragma unroll
        for (int r = 0; r < 4; r++) acc[r] = make_float4(0.f, 0.f, 0.f, 0.f);
        const int rmax = n - row0;

        #pragma unroll 4
        for (int k = 0; k < Fi; k += 4) {
            float4 xr[4];
            #pragma unroll
            for (int r = 0; r < 4; r++)
                xr[r] = (r < rmax)
                    ? *reinterpret_cast<const float4*>(&in[(size_t)(row0 + r) * Fi + k])
                    : make_float4(0.f, 0.f, 0.f, 0.f);
            #pragma unroll
            for (int kk = 0; kk < 4; kk++) {
                float4 w = *reinterpret_cast<const float4*>(&sWf[(k + kk) * Fo + 4 * c4]);
                #pragma unroll
                for (int r = 0; r < 4; r++) {
                    float xv = (kk == 0) ? xr[r].x : (kk == 1) ? xr[r].y : (kk == 2) ? xr[r].z : xr[r].w;
                    acc[r].x += xv * w.x; acc[r].y += xv * w.y;
                    acc[r].z += xv * w.z; acc[r].w += xv * w.w;
                }
            }
        }
        #pragma unroll
        for (int r = 0; r < 4; r++) {
            if (r < rmax) {
                int row = row0 + r;
                float4 a = acc[r];
                if (SCALE) {
                    float dv = g_dinv[row];
                    a.x *= dv; a.y *= dv; a.z *= dv; a.w *= dv;
                }
                __half2 h0 = __floats2half2_rn(a.x, a.y);
                __half2 h1 = __floats2half2_rn(a.z, a.w);
                uint2 u; u.x = *reinterpret_cast<unsigned*>(&h0);
                u.y = *reinterpret_cast<unsigned*>(&h1);
                *reinterpret_cast<uint2*>(outh + (size_t)row * Fo + 4 * c4) = u;
            }
        }
    }
}

// -------- standalone aggregation: out = dinv*tanh(dinv*agg+b), fp16 out --------
template<int F>
__global__ void __launch_bounds__(256) k_agg1(const __half* __restrict__ p,
                                              const float* __restrict__ bias,
                                              __half* __restrict__ outh, int n) {
    constexpr int TPN = F / 8;
    int t = blockIdx.x * 256 + threadIdx.x;
    int d = t / TPN;
    int c8 = t % TPN;
    if (d >= n) return;
    float s[8];
    gather8<TPN>(reinterpret_cast<const uint4*>(p), d, c8, s);
    float dv = g_dinv[d];
    const float* b = &bias[c8 * 8];
    float o[8];
    #pragma unroll
    for (int j = 0; j < 8; j++) o[j] = dv * tanhf(dv * s[j] + b[j]);
    *reinterpret_cast<uint4*>(outh + (size_t)d * F + c8 * 8) = pack8(o);
}

// -------- L2 fused (HMMA): v16 -> smem fp16 -> HMMA W2 hi/lo -> tanh,dinv -> fp16 --------
__global__ void __launch_bounds__(256) k_l2fused(const __half* __restrict__ p1,
                                                 const __half* __restrict__ Wt2,
                                                 const float* __restrict__ b2,
                                                 __half* __restrict__ outh, int n) {
    constexpr int AS = 24;         // Fi=16 + 8 pad
    constexpr int Fo = 128;
    __shared__ __half sA[128 * AS];    // v16 tile
    __shared__ __half sW[256 * AS];    // W2 hi/lo
    __shared__ float sB[128];
    const int t = threadIdx.x;
    const int base = blockIdx.x * 128;

    for (int i = t; i < 256 * AS / 8; i += 256)
        reinterpret_cast<uint4*>(sW)[i] = reinterpret_cast<const uint4*>(Wt2)[i];
    if (t < 128) sB[t] = b2[t];

    // phase A: v16 = dinv*(agg p1) -> fp16 smem (zero-fill OOB rows)
    {
        int r = t >> 1, c8 = t & 1;
        int row = base + r;
        uint4 val = make_uint4(0u, 0u, 0u, 0u);
        if (row < n) {
            float s[8];
            gather8<2>(reinterpret_cast<const uint4*>(p1), row, c8, s);
            float dv = g_dinv[row];
            float o[8];
            #pragma unroll
            for (int j = 0; j < 8; j++) o[j] = dv * s[j];
            val = pack8(o);
        }
        *reinterpret_cast<uint4*>(sA + r * AS + c8 * 8) = val;
    }
    __syncthreads();

    // phase B: HMMA Fi=16 (single k-step) -> Fo=128 (hi/lo)
    const int w = t >> 5, lane = t & 31;
    const int m0 = w * 16;
    constexpr int NT = Fo / 8;     // 16
    float acc[NT][4];
    #pragma unroll
    for (int j = 0; j < NT; j++) {
        acc[j][0] = 0.f; acc[j][1] = 0.f; acc[j][2] = 0.f; acc[j][3] = 0.f;
    }
    const int mm = lane >> 3;
    const int arow = m0 + (lane & 7) + 8 * (mm & 1);
    const int acol0 = 8 * (mm >> 1);
    const int brow = lane & 7;
    const int bnoff = (mm & 2) << 2;
    const int bkoff = (mm & 1) << 3;

    {
        uint32_t a0, a1, a2, a3;
        uint32_t saddr = (uint32_t)__cvta_generic_to_shared(sA + arow * AS + acol0);
        asm volatile("ldmatrix.sync.aligned.m8n8.x4.shared.b16 {%0,%1,%2,%3}, [%4];"
                     : "=r"(a0), "=r"(a1), "=r"(a2), "=r"(a3) : "r"(saddr));
        #pragma unroll
        for (int j = 0; j < NT; j += 2) {
            uint32_t b0, b1, b2, b3r;
            uint32_t baddr = (uint32_t)__cvta_generic_to_shared(
                sW + (j * 8 + bnoff + brow) * AS + bkoff);
            asm volatile("ldmatrix.sync.aligned.m8n8.x4.shared.b16 {%0,%1,%2,%3}, [%4];"
                         : "=r"(b0), "=r"(b1), "=r"(b2), "=r"(b3r) : "r"(baddr));
            asm volatile(
                "mma.sync.aligned.m16n8k16.row.col.f32.f16.f16.f32 "
                "{%0,%1,%2,%3}, {%4,%5,%6,%7}, {%8,%9}, {%0,%1,%2,%3};"
                : "+f"(acc[j][0]), "+f"(acc[j][1]), "+f"(acc[j][2]), "+f"(acc[j][3])
                : "r"(a0), "r"(a1), "r"(a2), "r"(a3), "r"(b0), "r"(b1));
            asm volatile(
                "mma.sync.aligned.m16n8k16.row.col.f32.f16.f16.f32 "
                "{%0,%1,%2,%3}, {%4,%5,%6,%7}, {%8,%9}, {%0,%1,%2,%3};"
                : "+f"(acc[j+1][0]), "+f"(acc[j+1][1]), "+f"(acc[j+1][2]), "+f"(acc[j+1][3])
                : "r"(a0), "r"(a1), "r"(a2), "r"(a3), "r"(b2), "r"(b3r));
            uint32_t c0, c1, c2, c3;
            uint32_t caddr = (uint32_t)__cvta_generic_to_shared(
                sW + ((128 + j * 8) + bnoff + brow) * AS + bkoff);
            asm volatile("ldmatrix.sync.aligned.m8n8.x4.shared.b16 {%0,%1,%2,%3}, [%4];"
                         : "=r"(c0), "=r"(c1), "=r"(c2), "=r"(c3) : "r"(caddr));
            asm volatile(
                "mma.sync.aligned.m16n8k16.row.col.f32.f16.f16.f32 "
                "{%0,%1,%2,%3}, {%4,%5,%6,%7}, {%8,%9}, {%0,%1,%2,%3};"
                : "+f"(acc[j][0]), "+f"(acc[j][1]), "+f"(acc[j][2]), "+f"(acc[j][3])
                : "r"(a0), "r"(a1), "r"(a2), "r"(a3), "r"(c0), "r"(c1));
            asm volatile(
                "mma.sync.aligned.m16n8k16.row.col.f32.f16.f16.f32 "
                "{%0,%1,%2,%3}, {%4,%5,%6,%7}, {%8,%9}, {%0,%1,%2,%3};"
                : "+f"(acc[j+1][0]), "+f"(acc[j+1][1]), "+f"(acc[j+1][2]), "+f"(acc[j+1][3])
                : "r"(a0), "r"(a1), "r"(a2), "r"(a3), "r"(c2), "r"(c3));
        }
    }

    // epilogue: p2 = dinv*tanh(acc + b2) -> fp16 global
    const int row0 = base + m0 + (lane >> 2);
    const int row1 = row0 + 8;
    const int col = (lane & 3) * 2;
    const float dv0 = (row0 < n) ? g_dinv[row0] : 0.f;
    const float dv1 = (row1 < n) ? g_dinv[row1] : 0.f;
    #pragma unroll
    for (int j = 0; j < NT; j++) {
        int ng = j * 8 + col;
        if (row0 < n) {
            float o0 = dv0 * tanhf(acc[j][0] + sB[ng]);
            float o1 = dv0 * tanhf(acc[j][1] + sB[ng + 1]);
            *reinterpret_cast<__half2*>(outh + (size_t)row0 * Fo + ng) = __floats2half2_rn(o0, o1);
        }
        if (row1 < n) {
            float o0 = dv1 * tanhf(acc[j][2] + sB[ng]);
            float o1 = dv1 * tanhf(acc[j][3] + sB[ng + 1]);
            *reinterpret_cast<__half2*>(outh + (size_t)row1 * Fo + ng) = __floats2half2_rn(o0, o1);
        }
    }
}

// -------- L5 fused: v64 -> smem fp16 -> HMMA W5 hi/lo -> tanh -> pool atomics --------
__global__ void __launch_bounds__(256) k_l5fused(const __half* __restrict__ p4in,
                                                 const __half* __restrict__ Wt5,
                                                 const float* __restrict__ b5,
                                                 const int* __restrict__ batch, int n) {
    constexpr int AS = 72;
    __shared__ __half sV[64 * AS];
    __shared__ __half sW[128 * AS];
    __shared__ float sB[64];
    int t = threadIdx.x;
    int base = blockIdx.x * 64;
    for (int i = t; i < 128 * AS / 8; i += 256)
        reinterpret_cast<uint4*>(sW)[i] = reinterpret_cast<const uint4*>(Wt5)[i];
    if (t < 64) sB[t] = b5[t];
    #pragma unroll
    for (int pass = 0; pass < 2; pass++) {
        int r = pass * 32 + (t >> 3);
        int c8 = t & 7;
        int row = base + r;
        uint4 val = make_uint4(0u, 0u, 0u, 0u);
        if (row < n) {
            float s[8];
            gather8<8>(reinterpret_cast<const uint4*>(p4in), row, c8, s);
            float dv = g_dinv[row];
            float o[8];
            #pragma unroll
            for (int j = 0; j < 8; j++) o[j] = dv * s[j];
            val = pack8(o);
        }
        *reinterpret_cast<uint4*>(sV + r * AS + c8 * 8) = val;
    }
    __syncthreads();

    const int w = t >> 5, lane = t & 31;
    const int mw = w & 3, nw = w >> 2;
    const int m0 = mw * 16;
    float acc[4][4];
    #pragma unroll
    for (int j = 0; j < 4; j++) {
        acc[j][0] = 0.f; acc[j][1] = 0.f; acc[j][2] = 0.f; acc[j][3] = 0.f;
    }
    const int mm = lane >> 3;
    const int arow = m0 + (lane & 7) + 8 * (mm & 1);
    const int acol0 = 8 * (mm >> 1);
    const int brow = lane & 7;
    const int bnoff = (mm & 2) << 2;
    const int bkoff = (mm & 1) << 3;

    #pragma unroll
    for (int k0 = 0; k0 < 64; k0 += 16) {
        uint32_t a0, a1, a2, a3;
        uint32_t saddr = (uint32_t)__cvta_generic_to_shared(sV + arow * AS + acol0 + k0);
        asm volatile("ldmatrix.sync.aligned.m8n8.x4.shared.b16 {%0,%1,%2,%3}, [%4];"
                     : "=r"(a0), "=r"(a1), "=r"(a2), "=r"(a3) : "r"(saddr));
        #pragma unroll
        for (int jl = 0; jl < 4; jl += 2) {
            int j = nw * 4 + jl;
            uint32_t b0, b1, b2, b3r;
            uint32_t baddr = (uint32_t)__cvta_generic_to_shared(
                sW + (j * 8 + bnoff + brow) * AS + k0 + bkoff);
            asm volatile("ldmatrix.sync.aligned.m8n8.x4.shared.b16 {%0,%1,%2,%3}, [%4];"
                         : "=r"(b0), "=r"(b1), "=r"(b2), "=r"(b3r) : "r"(baddr));
            asm volatile(
                "mma.sync.aligned.m16n8k16.row.col.f32.f16.f16.f32 "
                "{%0,%1,%2,%3}, {%4,%5,%6,%7}, {%8,%9}, {%0,%1,%2,%3};"
                : "+f"(acc[jl][0]), "+f"(acc[jl][1]), "+f"(acc[jl][2]), "+f"(acc[jl][3])
                : "r"(a0), "r"(a1), "r"(a2), "r"(a3), "r"(b0), "r"(b1));
            asm volatile(
                "mma.sync.aligned.m16n8k16.row.col.f32.f16.f16.f32 "
                "{%0,%1,%2,%3}, {%4,%5,%6,%7}, {%8,%9}, {%0,%1,%2,%3};"
                : "+f"(acc[jl+1][0]), "+f"(acc[jl+1][1]), "+f"(acc[jl+1][2]), "+f"(acc[jl+1][3])
                : "r"(a0), "r"(a1), "r"(a2), "r"(a3), "r"(b2), "r"(b3r));
            uint32_t c0, c1, c2, c3;
            uint32_t caddr = (uint32_t)__cvta_generic_to_shared(
                sW + ((64 + j * 8) + bnoff + brow) * AS + k0 + bkoff);
            asm volatile("ldmatrix.sync.aligned.m8n8.x4.shared.b16 {%0,%1,%2,%3}, [%4];"
                         : "=r"(c0), "=r"(c1), "=r"(c2), "=r"(c3) : "r"(caddr));
            asm volatile(
                "mma.sync.aligned.m16n8k16.row.col.f32.f16.f16.f32 "
                "{%0,%1,%2,%3}, {%4,%5,%6,%7}, {%8,%9}, {%0,%1,%2,%3};"
                : "+f"(acc[jl][0]), "+f"(acc[jl][1]), "+f"(acc[jl][2]), "+f"(acc[jl][3])
                : "r"(a0), "r"(a1), "r"(a2), "r"(a3), "r"(c0), "r"(c1));
            asm volatile(
                "mma.sync.aligned.m16n8k16.row.col.f32.f16.f16.f32 "
                "{%0,%1,%2,%3}, {%4,%5,%6,%7}, {%8,%9}, {%0,%1,%2,%3};"
                : "+f"(acc[jl+1][0]), "+f"(acc[jl+1][1]), "+f"(acc[jl+1][2]), "+f"(acc[jl+1][3])
                : "r"(a0), "r"(a1), "r"(a2), "r"(a3), "r"(c2), "r"(c3));
        }
    }

    const int row0 = base + m0 + (lane >> 2);
    const int row1 = row0 + 8;
    const int col = (lane & 3) * 2;
    const int g0 = (row0 < n) ? batch[row0] : 0;
    const int g1 = (row1 < n) ? batch[row1] : 0;
    #pragma unroll
    for (int jl = 0; jl < 4; jl++) {
        int ng = (nw * 4 + jl) * 8 + col;
        if (row0 < n) {
            atomicAdd(&g_pool[g0 * 64 + ng],     tanhf(acc[jl][0] + sB[ng]));
            atomicAdd(&g_pool[g0 * 64 + ng + 1], tanhf(acc[jl][1] + sB[ng + 1]));
        }
        if (row1 < n) {
            atomicAdd(&g_pool[g1 * 64 + ng],     tanhf(acc[jl][2] + sB[ng]));
            atomicAdd(&g_pool[g1 * 64 + ng + 1], tanhf(acc[jl][3] + sB[ng + 1]));
        }
    }
    if (nw == 0 && (lane & 3) == 0) {
        if (row0 < n) atomicAdd(&g_cnt[g0], 1);
        if (row1 < n) atomicAdd(&g_cnt[g1], 1);
    }
}

__global__ void k_final(const float* __restrict__ Wc, const float* __restrict__ bc,
                        float* __restrict__ out) {
    int warp = (blockIdx.x * blockDim.x + threadIdx.x) / 32;
    int lane = threadIdx.x & 31;
    if (warp >= 128) return;
    float c = fmaxf((float)g_cnt[warp], 1.f);
    float s = g_pool[warp * 64 + lane] * Wc[lane] + g_pool[warp * 64 + lane + 32] * Wc[lane + 32];
    #pragma unroll
    for (int off = 16; off; off >>= 1) s += __shfl_down_sync(0xffffffffu, s, off);
    if (lane == 0) out[warp] = s / c + bc[0];
}

// -------- host side --------
static float* symA() { static float* p = nullptr; if (!p) cudaGetSymbolAddress((void**)&p, g_bufA); return p; }
static float* symB() { static float* p = nullptr; if (!p) cudaGetSymbolAddress((void**)&p, g_bufB); return p; }
static __half* symW2() { static __half* p = nullptr; if (!p) cudaGetSymbolAddress((void**)&p, g_W2h); return p; }
static __half* symW3() { static __half* p = nullptr; if (!p) cudaGetSymbolAddress((void**)&p, g_W3h); return p; }
static __half* symW4() { static __half* p = nullptr; if (!p) cudaGetSymbolAddress((void**)&p, g_W4h); return p; }
static __half* symW5() { static __half* p = nullptr; if (!p) cudaGetSymbolAddress((void**)&p, g_W5h); return p; }

extern "C" void kernel_launch(void* const* d_in, const int* in_sizes, int n_in,
                              void* d_out, int out_size) {
    const float* x     = (const float*)d_in[0];
    const int*   ei    = (const int*)d_in[1];     // int32 (JAX x64 disabled)
    const int*   batch = (const int*)d_in[2];     // int32
    const float* W1 = (const float*)d_in[3];  const float* b1 = (const float*)d_in[4];
    const float* W2 = (const float*)d_in[5];  const float* b2 = (const float*)d_in[6];
    const float* W3 = (const float*)d_in[7];  const float* b3 = (const float*)d_in[8];
    const float* W4 = (const float*)d_in[9];  const float* b4 = (const float*)d_in[10];
    const float* W5 = (const float*)d_in[11]; const float* b5 = (const float*)d_in[12];
    const float* Wc = (const float*)d_in[13]; const float* bc = (const float*)d_in[14];
    float* out = (float*)d_out;

    const int n = in_sizes[0] / 64;
    const int E = in_sizes[1] / 2;
    const int NB = (n + 255) / 256;

    __half* Ah = (__half*)symA();
    __half* Bh = (__half*)symB();

    constexpr int SM3  = (128 + 256) * 136 * 2;  // 104448 B (A + W3 hi/lo)
    constexpr int SM34 = (128 + 128) * 136 * 2;  // 69632 B  (p3 tile + W4 hi/lo)
    static bool attr_done = []() {
        cudaFuncSetAttribute((const void*)k_hmma<128, 128>,
                             cudaFuncAttributeMaxDynamicSharedMemorySize, SM3);
        cudaFuncSetAttribute((const void*)k_l34,
                             cudaFuncAttributeMaxDynamicSharedMemorySize, SM34);
        return true;
    }();
    (void)attr_done;

    // ---- CSR build + weight conversion ----
    k_init<<<512, 256>>>(W2, W3, W4, W5, n);
    k_count<<<(E + 255) / 256, 256>>>(ei, E);
    k_scan1<<<NB, 256>>>(n);
    k_scan2<<<1, 512>>>(NB);
    k_scan3<<<NB, 256>>>(n, E);
    k_fill<<<(E + 255) / 256, 256>>>(ei, E);

    auto ablocks = [&](int F) { return (n * (F / 8) + 255) / 256; };

    // L1: 64->16 scalar transform-first: Ah = fp16(dinv * (x @ W1))
    k_gemm<64, 16, true><<<(n + 255) / 256, 256, 64 * 16 * 4>>>(x, W1, Ah, n);
    k_agg1<16><<<ablocks(16), 256>>>(Ah, b1, Bh, n);                 // Bh = p1

    // L2 fused (HMMA): agg(p1) -> v16 smem -> HMMA W2 -> tanh,dinv -> Ah = p2
    k_l2fused<<<(n + 127) / 128, 256>>>(Bh, symW2(), b2, Ah, n);

    // L3: 128->128 HMMA hi/lo -> Bh = h3
    k_hmma<128, 128><<<(n + 127) / 128, 256, SM3>>>(Ah, symW3(), Bh, n);

    // L3agg + L4 GEMM fused: gather h3, tanh -> p3 (smem) -> HMMA W4 -> Ah = h4
    k_l34<<<(n + 127) / 128, 256, SM34>>>(Bh, symW4(), b3, Ah, n);

    // L4 agg: Ah (h4) -> Bh = p4
    k_agg1<64><<<ablocks(64), 256>>>(Ah, b4, Bh, n);

    // L5 fused: agg(p4) -> HMMA W5 -> tanh -> pool atomics
    k_l5fused<<<(n + 63) / 64, 256>>>(Bh, symW5(), b5, batch, n);

    // ---- head ----
    k_final<<<32, 128>>>(Wc, bc, out);
    (void)out_size; (void)n_in;
}